// round 2
// baseline (speedup 1.0000x reference)
#include <cuda_runtime.h>
#include <math.h>

// Problem constants (fixed shapes)
#define B_   8
#define H_   64
#define W_   64
#define HW_  4096          // H*W
#define M_   32768         // B*HW
#define C_   192
#define QKVC 576
#define HD   64            // head dim / branch dim
#define KK_  9

// ---------------------------------------------------------------------------
// Scratch (static device globals — no allocation at runtime)
// ---------------------------------------------------------------------------
__device__ float g_qkv[M_ * QKVC];      // [pos][576]  (q0..2 | k0..2 | v0..2, 64 ch each)
__device__ float g_off[M_ * 18];        // [pos][18]   reused per dilation
__device__ float g_sampk[M_ * QKVC];    // [pos][kk*64+c]
__device__ float g_sampv[M_ * QKVC];
__device__ float g_defk2[M_ * HD];
__device__ float g_defv2[M_ * HD];
__device__ float g_defk3[M_ * HD];
__device__ float g_defv3[M_ * HD];
__device__ float g_attn[M_ * C_];       // [pos][branch*64+c]
__device__ float g_defWt[HD * QKVC];    // def_w transposed to [o][kk*64+c]

// ---------------------------------------------------------------------------
// Generic NT SGEMM: C[m,n] = sum_k A[m,k] * Wt[n,k] (+ bias[n])
// 64x64 tile, 256 threads, 4x4 microtile, TK=16. M multiple of 64, N multiple
// of 64, K multiple of 16 (all true for every call here).
// ---------------------------------------------------------------------------
__global__ __launch_bounds__(256) void sgemm_nt(
    const float* __restrict__ A, const float* __restrict__ Wt,
    const float* __restrict__ bias, float* __restrict__ C,
    int N, int Kd)
{
    __shared__ __align__(16) float As[16][68];   // pad 68 -> 272B rows (16B aligned)
    __shared__ __align__(16) float Bs[16][68];

    const int tid = threadIdx.x;
    const int tx = tid & 15, ty = tid >> 4;
    const int m0 = blockIdx.y * 64;
    const int n0 = blockIdx.x * 64;

    float acc[4][4] = {};

    for (int k0 = 0; k0 < Kd; k0 += 16) {
        #pragma unroll
        for (int i = 0; i < 4; i++) {
            int e = tid + i * 256;        // 0..1023
            int m = e >> 4;               // 0..63
            int kk = e & 15;              // 0..15
            As[kk][m] = A [(size_t)(m0 + m) * Kd + k0 + kk];
            Bs[kk][m] = Wt[(size_t)(n0 + m) * Kd + k0 + kk];
        }
        __syncthreads();
        #pragma unroll
        for (int kk = 0; kk < 16; kk++) {
            float4 av = *reinterpret_cast<const float4*>(&As[kk][ty * 4]);
            float4 bv = *reinterpret_cast<const float4*>(&Bs[kk][tx * 4]);
            float a[4] = {av.x, av.y, av.z, av.w};
            float b[4] = {bv.x, bv.y, bv.z, bv.w};
            #pragma unroll
            for (int i = 0; i < 4; i++)
                #pragma unroll
                for (int j = 0; j < 4; j++)
                    acc[i][j] += a[i] * b[j];
        }
        __syncthreads();
    }

    #pragma unroll
    for (int i = 0; i < 4; i++) {
        int row = m0 + ty * 4 + i;
        #pragma unroll
        for (int j = 0; j < 4; j++) {
            int col = n0 + tx * 4 + j;
            float v = acc[i][j];
            if (bias) v += bias[col];
            C[(size_t)row * N + col] = v;
        }
    }
}

// ---------------------------------------------------------------------------
// Dilated 3x3 conv producing 18 offset channels. One thread per position.
// Weights (18,64,3,3) staged in smem (broadcast reads).
// ---------------------------------------------------------------------------
__global__ __launch_bounds__(128) void off_conv(
    const float* __restrict__ qkv, int kbase,
    const float* __restrict__ wgt, const float* __restrict__ bias,
    float* __restrict__ out, int dil)
{
    __shared__ float ws[18 * 576];
    for (int i = threadIdx.x; i < 18 * 576; i += blockDim.x) ws[i] = wgt[i];
    __syncthreads();

    int pos = blockIdx.x * blockDim.x + threadIdx.x;
    int b = pos >> 12, hw = pos & 4095, h = hw >> 6, x = hw & 63;

    float acc[18];
    #pragma unroll
    for (int o = 0; o < 18; o++) acc[o] = bias[o];

    for (int ky = 0; ky < 3; ky++) {
        int y = h + (ky - 1) * dil;
        if (y < 0 || y >= H_) continue;
        for (int kx = 0; kx < 3; kx++) {
            int xx = x + (kx - 1) * dil;
            if (xx < 0 || xx >= W_) continue;
            const float* kp = qkv + ((size_t)((b << 12) + (y << 6) + xx)) * QKVC + kbase;
            int kkk = ky * 3 + kx;
            for (int c = 0; c < 64; c++) {
                float kv = kp[c];
                const float* wp = &ws[c * 9 + kkk];
                #pragma unroll
                for (int o = 0; o < 18; o++) acc[o] += kv * wp[o * 576];
            }
        }
    }
    float* op = out + (size_t)pos * 18;
    #pragma unroll
    for (int o = 0; o < 18; o++) op[o] = acc[o];
}

// ---------------------------------------------------------------------------
// def_w (64,64,3,3) row-major [o][c][kk]  ->  [o][kk*64+c]
// ---------------------------------------------------------------------------
__global__ void wtrans(const float* __restrict__ w, float* __restrict__ wt)
{
    int i = blockIdx.x * blockDim.x + threadIdx.x;
    if (i >= 64 * 576) return;
    int o = i / 576, r = i % 576, c = r / 9, kk = r % 9;
    wt[o * 576 + kk * 64 + c] = w[i];
}

// ---------------------------------------------------------------------------
// Bilinear sampling of k and v (shared offsets). One block per position,
// 9 warps = 9 taps, 2 channels per lane. Matches reference corner masking.
// ---------------------------------------------------------------------------
__global__ __launch_bounds__(288) void sample_kv(
    const float* __restrict__ qkv, int kbase, int vbase,
    const float* __restrict__ off,
    float* __restrict__ sk, float* __restrict__ sv, int dil)
{
    int pos = blockIdx.x;
    int kk = threadIdx.x >> 5;
    int lane = threadIdx.x & 31;
    int b = pos >> 12, hw = pos & 4095, h = hw >> 6, x = hw & 63;

    float offy = off[(size_t)pos * 18 + 2 * kk];
    float offx = off[(size_t)pos * 18 + 2 * kk + 1];
    float py = (float)h + (float)((kk / 3 - 1) * dil) + offy;
    float px = (float)x + (float)((kk % 3 - 1) * dil) + offx;

    float y0f = floorf(py), x0f = floorf(px);
    float wy = py - y0f, wx = px - x0f;
    int y0 = (int)y0f, x0 = (int)x0f;
    int y1 = y0 + 1, x1 = x0 + 1;

    float w00 = (1.f - wy) * (1.f - wx);
    float w01 = (1.f - wy) * wx;
    float w10 = wy * (1.f - wx);
    float w11 = wy * wx;

    bool v00 = (y0 >= 0 && y0 < H_ && x0 >= 0 && x0 < W_);
    bool v01 = (y0 >= 0 && y0 < H_ && x1 >= 0 && x1 < W_);
    bool v10 = (y1 >= 0 && y1 < H_ && x0 >= 0 && x0 < W_);
    bool v11 = (y1 >= 0 && y1 < H_ && x1 >= 0 && x1 < W_);

    size_t base = (size_t)(b << 12);
    size_t i00 = (base + (y0 << 6) + x0) * QKVC;
    size_t i01 = (base + (y0 << 6) + x1) * QKVC;
    size_t i10 = (base + (y1 << 6) + x0) * QKVC;
    size_t i11 = (base + (y1 << 6) + x1) * QKVC;

    #pragma unroll
    for (int half = 0; half < 2; half++) {
        int c = lane + half * 32;
        float ak = 0.f, av = 0.f;
        if (v00) { ak += w00 * qkv[i00 + kbase + c]; av += w00 * qkv[i00 + vbase + c]; }
        if (v01) { ak += w01 * qkv[i01 + kbase + c]; av += w01 * qkv[i01 + vbase + c]; }
        if (v10) { ak += w10 * qkv[i10 + kbase + c]; av += w10 * qkv[i10 + vbase + c]; }
        if (v11) { ak += w11 * qkv[i11 + kbase + c]; av += w11 * qkv[i11 + vbase + c]; }
        sk[(size_t)pos * QKVC + kk * 64 + c] = ak;
        sv[(size_t)pos * QKVC + kk * 64 + c] = av;
    }
}

// ---------------------------------------------------------------------------
// 9-tap local attention. One warp per position; lane covers channels c, c+32.
// OOB taps contribute logit==0 (zero-padded unfold) and v==0.
// ---------------------------------------------------------------------------
__global__ __launch_bounds__(256) void attn_kernel(
    const float* __restrict__ qb, int qofs,
    const float* __restrict__ kb, int kstride, int kofs,
    const float* __restrict__ vb, int vstride, int vofs,
    float* __restrict__ ob, int dil)
{
    int warp = threadIdx.x >> 5, lane = threadIdx.x & 31;
    int pos = (blockIdx.x << 3) + warp;
    int b = pos >> 12, hw = pos & 4095, h = hw >> 6, x = hw & 63;

    float q0 = qb[(size_t)pos * QKVC + qofs + lane];
    float q1 = qb[(size_t)pos * QKVC + qofs + lane + 32];

    float logits[9];
    #pragma unroll
    for (int kk = 0; kk < 9; kk++) {
        int y = h + (kk / 3 - 1) * dil;
        int xx = x + (kk % 3 - 1) * dil;
        float p = 0.f;
        if (y >= 0 && y < H_ && xx >= 0 && xx < W_) {
            const float* kp = kb + (size_t)((b << 12) + (y << 6) + xx) * kstride + kofs;
            p = q0 * kp[lane] + q1 * kp[lane + 32];
        }
        #pragma unroll
        for (int s = 16; s; s >>= 1) p += __shfl_xor_sync(0xffffffffu, p, s);
        logits[kk] = p * 0.125f;   // head_dim^-0.5 = 1/8
    }

    float mx = logits[0];
    #pragma unroll
    for (int kk = 1; kk < 9; kk++) mx = fmaxf(mx, logits[kk]);
    float e[9], den = 0.f;
    #pragma unroll
    for (int kk = 0; kk < 9; kk++) { e[kk] = expf(logits[kk] - mx); den += e[kk]; }
    float inv = 1.f / den;

    float o0 = 0.f, o1 = 0.f;
    #pragma unroll
    for (int kk = 0; kk < 9; kk++) {
        int y = h + (kk / 3 - 1) * dil;
        int xx = x + (kk % 3 - 1) * dil;
        if (y >= 0 && y < H_ && xx >= 0 && xx < W_) {
            const float* vp = vb + (size_t)((b << 12) + (y << 6) + xx) * vstride + vofs;
            float a = e[kk] * inv;
            o0 += a * vp[lane];
            o1 += a * vp[lane + 32];
        }
    }
    ob[(size_t)pos * C_ + lane]      = o0;
    ob[(size_t)pos * C_ + lane + 32] = o1;
}

// ---------------------------------------------------------------------------
// Launch
// ---------------------------------------------------------------------------
extern "C" void kernel_launch(void* const* d_in, const int* in_sizes, int n_in,
                              void* d_out, int out_size)
{
    const float* x      = (const float*)d_in[0];
    const float* qkv_w  = (const float*)d_in[1];
    const float* proj_w = (const float*)d_in[2];
    const float* proj_b = (const float*)d_in[3];
    const float* off_w2 = (const float*)d_in[4];
    const float* off_b2 = (const float*)d_in[5];
    const float* def_w2 = (const float*)d_in[6];
    const float* def_b2 = (const float*)d_in[7];
    const float* off_w3 = (const float*)d_in[8];
    const float* off_b3 = (const float*)d_in[9];
    const float* def_w3 = (const float*)d_in[10];
    const float* def_b3 = (const float*)d_in[11];
    float* out = (float*)d_out;

    float *p_qkv, *p_off, *p_sk, *p_sv, *p_dk2, *p_dv2, *p_dk3, *p_dv3, *p_attn, *p_wt;
    cudaGetSymbolAddress((void**)&p_qkv,  g_qkv);
    cudaGetSymbolAddress((void**)&p_off,  g_off);
    cudaGetSymbolAddress((void**)&p_sk,   g_sampk);
    cudaGetSymbolAddress((void**)&p_sv,   g_sampv);
    cudaGetSymbolAddress((void**)&p_dk2,  g_defk2);
    cudaGetSymbolAddress((void**)&p_dv2,  g_defv2);
    cudaGetSymbolAddress((void**)&p_dk3,  g_defk3);
    cudaGetSymbolAddress((void**)&p_dv3,  g_defv3);
    cudaGetSymbolAddress((void**)&p_attn, g_attn);
    cudaGetSymbolAddress((void**)&p_wt,   g_defWt);

    // 1) qkv = x @ qkv_w^T   [32768 x 192] x [576 x 192]^T
    sgemm_nt<<<dim3(QKVC / 64, M_ / 64), 256>>>(x, qkv_w, nullptr, p_qkv, QKVC, C_);

    // 2) deformable branches (dil = 2, 3)
    struct Br { int dil; const float *ow, *ob, *dw, *db; float *dk, *dv; };
    Br br[2] = {
        {2, off_w2, off_b2, def_w2, def_b2, p_dk2, p_dv2},
        {3, off_w3, off_b3, def_w3, def_b3, p_dk3, p_dv3},
    };
    for (int t = 0; t < 2; t++) {
        int i = t + 1;
        int kbase = 192 + i * 64;
        int vbase = 384 + i * 64;
        off_conv<<<M_ / 128, 128>>>(p_qkv, kbase, br[t].ow, br[t].ob, p_off, br[t].dil);
        wtrans<<<(64 * 576 + 255) / 256, 256>>>(br[t].dw, p_wt);
        sample_kv<<<M_, 288>>>(p_qkv, kbase, vbase, p_off, p_sk, p_sv, br[t].dil);
        sgemm_nt<<<dim3(1, M_ / 64), 256>>>(p_sk, p_wt, br[t].db, br[t].dk, HD, QKVC);
        sgemm_nt<<<dim3(1, M_ / 64), 256>>>(p_sv, p_wt, br[t].db, br[t].dv, HD, QKVC);
    }

    // 3) attention per branch -> g_attn [pos][branch*64+c]
    attn_kernel<<<M_ / 8, 256>>>(p_qkv, 0,   p_qkv, QKVC, 192, p_qkv, QKVC, 384, p_attn,       1);
    attn_kernel<<<M_ / 8, 256>>>(p_qkv, 64,  p_dk2, HD,   0,   p_dv2, HD,   0,   p_attn + 64,  2);
    attn_kernel<<<M_ / 8, 256>>>(p_qkv, 128, p_dk3, HD,   0,   p_dv3, HD,   0,   p_attn + 128, 3);

    // 4) out = attn @ proj_w^T + proj_b
    sgemm_nt<<<dim3(C_ / 64, M_ / 64), 256>>>(p_attn, proj_w, proj_b, out, C_, C_);
}

// round 3
// speedup vs baseline: 1.7102x; 1.7102x over previous
#include <cuda_runtime.h>
#include <math.h>

// Problem constants (fixed shapes)
#define B_   8
#define H_   64
#define W_   64
#define HW_  4096
#define M_   32768         // B*HW
#define C_   192
#define QKVC 576
#define HD   64
#define KK_  9

// ---------------------------------------------------------------------------
// Scratch (static device globals)
// ---------------------------------------------------------------------------
__device__ float g_qkv[M_ * QKVC];      // [pos][576]  (q0..2 | k0..2 | v0..2)
__device__ float g_off[M_ * 18];
__device__ float g_sampk[M_ * QKVC];    // [pos][kk*64+c]
__device__ float g_sampv[M_ * QKVC];
__device__ float g_defk2[M_ * HD];
__device__ float g_defv2[M_ * HD];
__device__ float g_defk3[M_ * HD];
__device__ float g_defv3[M_ * HD];
__device__ float g_attn[M_ * C_];       // [pos][branch*64+c]
__device__ float g_defWt[HD * QKVC];    // def_w transposed to [o][kk*64+c]

// ---------------------------------------------------------------------------
// tf32 helpers
// ---------------------------------------------------------------------------
__device__ __forceinline__ unsigned f2tf32(float f) {
    unsigned u;
    asm("cvt.rna.tf32.f32 %0, %1;" : "=r"(u) : "f"(f));
    return u;
}

__device__ __forceinline__ void mma_tf32(float (&d)[4], const unsigned (&a)[4],
                                         const unsigned (&b)[2]) {
    asm volatile(
        "mma.sync.aligned.m16n8k8.row.col.f32.tf32.tf32.f32 "
        "{%0,%1,%2,%3}, {%4,%5,%6,%7}, {%8,%9}, {%0,%1,%2,%3};\n"
        : "+f"(d[0]), "+f"(d[1]), "+f"(d[2]), "+f"(d[3])
        : "r"(a[0]), "r"(a[1]), "r"(a[2]), "r"(a[3]), "r"(b[0]), "r"(b[1]));
}

// ---------------------------------------------------------------------------
// Tensor-core NT GEMM (tf32): C[m,n] = sum_k A[m,k] * Wt[n,k] (+ bias[n])
// Block tile 128x64, 4 warps (2x2), warp tile 64x32, BK=16, double-buffered.
// M % 128 == 0, N % 64 == 0, K % 16 == 0 (true for every call here).
// ---------------------------------------------------------------------------
#define BM 128
#define BN 64
#define BK 16
#define PAD 20

__global__ __launch_bounds__(128) void mma_nt(
    const float* __restrict__ A, const float* __restrict__ Wt,
    const float* __restrict__ bias, float* __restrict__ C,
    int N, int Kd)
{
    __shared__ __align__(16) unsigned As[2][BM * PAD];
    __shared__ __align__(16) unsigned Bs[2][BN * PAD];

    const int tid  = threadIdx.x;
    const int lane = tid & 31;
    const int warp = tid >> 5;
    const int wm = warp >> 1, wn = warp & 1;
    const int g = lane >> 2, t = lane & 3;
    const int m0 = blockIdx.y * BM;
    const int n0 = blockIdx.x * BN;

    float acc[4][4][4] = {};

    const int nit = Kd / BK;
    float4 ra[4], rb[2];

    // prefetch iter 0
    #pragma unroll
    for (int i = 0; i < 4; i++) {
        int f = tid + i * 128, row = f >> 2, kq = f & 3;
        ra[i] = *reinterpret_cast<const float4*>(&A[(size_t)(m0 + row) * Kd + kq * 4]);
    }
    #pragma unroll
    for (int i = 0; i < 2; i++) {
        int f = tid + i * 128, row = f >> 2, kq = f & 3;
        rb[i] = *reinterpret_cast<const float4*>(&Wt[(size_t)(n0 + row) * Kd + kq * 4]);
    }
    // store buf 0
    #pragma unroll
    for (int i = 0; i < 4; i++) {
        int f = tid + i * 128, row = f >> 2, kq = f & 3;
        unsigned* p = &As[0][row * PAD + kq * 4];
        p[0] = f2tf32(ra[i].x); p[1] = f2tf32(ra[i].y);
        p[2] = f2tf32(ra[i].z); p[3] = f2tf32(ra[i].w);
    }
    #pragma unroll
    for (int i = 0; i < 2; i++) {
        int f = tid + i * 128, row = f >> 2, kq = f & 3;
        unsigned* p = &Bs[0][row * PAD + kq * 4];
        p[0] = f2tf32(rb[i].x); p[1] = f2tf32(rb[i].y);
        p[2] = f2tf32(rb[i].z); p[3] = f2tf32(rb[i].w);
    }
    __syncthreads();

    for (int it = 0; it < nit; it++) {
        const int buf = it & 1;
        const bool more = (it + 1) < nit;
        if (more) {
            int k0 = (it + 1) * BK;
            #pragma unroll
            for (int i = 0; i < 4; i++) {
                int f = tid + i * 128, row = f >> 2, kq = f & 3;
                ra[i] = *reinterpret_cast<const float4*>(&A[(size_t)(m0 + row) * Kd + k0 + kq * 4]);
            }
            #pragma unroll
            for (int i = 0; i < 2; i++) {
                int f = tid + i * 128, row = f >> 2, kq = f & 3;
                rb[i] = *reinterpret_cast<const float4*>(&Wt[(size_t)(n0 + row) * Kd + k0 + kq * 4]);
            }
        }

        #pragma unroll
        for (int ks = 0; ks < 16; ks += 8) {
            unsigned af[4][4], bf[4][2];
            #pragma unroll
            for (int mi = 0; mi < 4; mi++) {
                int r = wm * 64 + mi * 16 + g;
                af[mi][0] = As[buf][r * PAD + ks + t];
                af[mi][1] = As[buf][(r + 8) * PAD + ks + t];
                af[mi][2] = As[buf][r * PAD + ks + t + 4];
                af[mi][3] = As[buf][(r + 8) * PAD + ks + t + 4];
            }
            #pragma unroll
            for (int nj = 0; nj < 4; nj++) {
                int cc = wn * 32 + nj * 8 + g;
                bf[nj][0] = Bs[buf][cc * PAD + ks + t];
                bf[nj][1] = Bs[buf][cc * PAD + ks + t + 4];
            }
            #pragma unroll
            for (int mi = 0; mi < 4; mi++)
                #pragma unroll
                for (int nj = 0; nj < 4; nj++)
                    mma_tf32(acc[mi][nj], af[mi], bf[nj]);
        }

        if (more) {
            const int nb = (it + 1) & 1;
            #pragma unroll
            for (int i = 0; i < 4; i++) {
                int f = tid + i * 128, row = f >> 2, kq = f & 3;
                unsigned* p = &As[nb][row * PAD + kq * 4];
                p[0] = f2tf32(ra[i].x); p[1] = f2tf32(ra[i].y);
                p[2] = f2tf32(ra[i].z); p[3] = f2tf32(ra[i].w);
            }
            #pragma unroll
            for (int i = 0; i < 2; i++) {
                int f = tid + i * 128, row = f >> 2, kq = f & 3;
                unsigned* p = &Bs[nb][row * PAD + kq * 4];
                p[0] = f2tf32(rb[i].x); p[1] = f2tf32(rb[i].y);
                p[2] = f2tf32(rb[i].z); p[3] = f2tf32(rb[i].w);
            }
            __syncthreads();
        }
    }

    // epilogue
    #pragma unroll
    for (int mi = 0; mi < 4; mi++) {
        int r = m0 + wm * 64 + mi * 16 + g;
        #pragma unroll
        for (int nj = 0; nj < 4; nj++) {
            int c = n0 + wn * 32 + nj * 8 + 2 * t;
            float b0 = bias ? bias[c] : 0.f;
            float b1 = bias ? bias[c + 1] : 0.f;
            float2 lo = make_float2(acc[mi][nj][0] + b0, acc[mi][nj][1] + b1);
            float2 hi = make_float2(acc[mi][nj][2] + b0, acc[mi][nj][3] + b1);
            *reinterpret_cast<float2*>(&C[(size_t)r * N + c]) = lo;
            *reinterpret_cast<float2*>(&C[(size_t)(r + 8) * N + c]) = hi;
        }
    }
}

// ---------------------------------------------------------------------------
// Dilated 3x3 conv producing 18 offset channels. One thread per position.
// ---------------------------------------------------------------------------
__global__ __launch_bounds__(128) void off_conv(
    const float* __restrict__ qkv, int kbase,
    const float* __restrict__ wgt, const float* __restrict__ bias,
    float* __restrict__ out, int dil)
{
    __shared__ float ws[18 * 576];
    for (int i = threadIdx.x; i < 18 * 576; i += blockDim.x) ws[i] = wgt[i];
    __syncthreads();

    int pos = blockIdx.x * blockDim.x + threadIdx.x;
    int b = pos >> 12, hw = pos & 4095, h = hw >> 6, x = hw & 63;

    float acc[18];
    #pragma unroll
    for (int o = 0; o < 18; o++) acc[o] = bias[o];

    for (int ky = 0; ky < 3; ky++) {
        int y = h + (ky - 1) * dil;
        if (y < 0 || y >= H_) continue;
        for (int kx = 0; kx < 3; kx++) {
            int xx = x + (kx - 1) * dil;
            if (xx < 0 || xx >= W_) continue;
            const float* kp = qkv + ((size_t)((b << 12) + (y << 6) + xx)) * QKVC + kbase;
            int kkk = ky * 3 + kx;
            for (int c = 0; c < 64; c++) {
                float kv = kp[c];
                const float* wp = &ws[c * 9 + kkk];
                #pragma unroll
                for (int o = 0; o < 18; o++) acc[o] += kv * wp[o * 576];
            }
        }
    }
    float* op = out + (size_t)pos * 18;
    #pragma unroll
    for (int o = 0; o < 18; o++) op[o] = acc[o];
}

// ---------------------------------------------------------------------------
// def_w (64,64,3,3) [o][c][kk] -> [o][kk*64+c]
// ---------------------------------------------------------------------------
__global__ void wtrans(const float* __restrict__ w, float* __restrict__ wt)
{
    int i = blockIdx.x * blockDim.x + threadIdx.x;
    if (i >= 64 * 576) return;
    int o = i / 576, r = i % 576, c = r / 9, kk = r % 9;
    wt[o * 576 + kk * 64 + c] = w[i];
}

// ---------------------------------------------------------------------------
// Bilinear sampling of k and v. One warp per (pos, tap); lane covers
// (array = k|v, 4-channel group) -> 4x LDG.128 + 1x STG.128 per thread.
// ---------------------------------------------------------------------------
__global__ __launch_bounds__(288) void sample_kv(
    const float* __restrict__ qkv, int kbase,
    const float* __restrict__ off,
    float* __restrict__ sk, float* __restrict__ sv, int dil)
{
    int pos = blockIdx.x;
    int kk = threadIdx.x >> 5;
    int lane = threadIdx.x & 31;
    int b = pos >> 12, hw = pos & 4095, h = hw >> 6, x = hw & 63;

    float offy = off[(size_t)pos * 18 + 2 * kk];
    float offx = off[(size_t)pos * 18 + 2 * kk + 1];
    float py = (float)h + (float)((kk / 3 - 1) * dil) + offy;
    float px = (float)x + (float)((kk % 3 - 1) * dil) + offx;

    float y0f = floorf(py), x0f = floorf(px);
    float wy = py - y0f, wx = px - x0f;
    int y0 = (int)y0f, x0 = (int)x0f;
    int y1 = y0 + 1, x1 = x0 + 1;

    float w00 = (1.f - wy) * (1.f - wx);
    float w01 = (1.f - wy) * wx;
    float w10 = wy * (1.f - wx);
    float w11 = wy * wx;

    bool v00 = (y0 >= 0 && y0 < H_ && x0 >= 0 && x0 < W_);
    bool v01 = (y0 >= 0 && y0 < H_ && x1 >= 0 && x1 < W_);
    bool v10 = (y1 >= 0 && y1 < H_ && x0 >= 0 && x0 < W_);
    bool v11 = (y1 >= 0 && y1 < H_ && x1 >= 0 && x1 < W_);

    size_t base = (size_t)(b << 12);
    int arr = lane >> 4;                 // 0 = k, 1 = v (vbase = kbase + 192)
    int c4 = (lane & 15) * 4;
    int chofs = kbase + arr * 192 + c4;

    size_t i00 = (base + (y0 << 6) + x0) * QKVC + chofs;
    size_t i01 = (base + (y0 << 6) + x1) * QKVC + chofs;
    size_t i10 = (base + (y1 << 6) + x0) * QKVC + chofs;
    size_t i11 = (base + (y1 << 6) + x1) * QKVC + chofs;

    float4 acc = make_float4(0.f, 0.f, 0.f, 0.f);
    if (v00) { float4 u = *reinterpret_cast<const float4*>(&qkv[i00]);
        acc.x += w00 * u.x; acc.y += w00 * u.y; acc.z += w00 * u.z; acc.w += w00 * u.w; }
    if (v01) { float4 u = *reinterpret_cast<const float4*>(&qkv[i01]);
        acc.x += w01 * u.x; acc.y += w01 * u.y; acc.z += w01 * u.z; acc.w += w01 * u.w; }
    if (v10) { float4 u = *reinterpret_cast<const float4*>(&qkv[i10]);
        acc.x += w10 * u.x; acc.y += w10 * u.y; acc.z += w10 * u.z; acc.w += w10 * u.w; }
    if (v11) { float4 u = *reinterpret_cast<const float4*>(&qkv[i11]);
        acc.x += w11 * u.x; acc.y += w11 * u.y; acc.z += w11 * u.z; acc.w += w11 * u.w; }

    float* dst = arr ? sv : sk;
    *reinterpret_cast<float4*>(&dst[(size_t)pos * QKVC + kk * 64 + c4]) = acc;
}

// ---------------------------------------------------------------------------
// 9-tap local attention. One warp per position; lane covers channels c, c+32.
// ---------------------------------------------------------------------------
__global__ __launch_bounds__(256) void attn_kernel(
    const float* __restrict__ qb, int qofs,
    const float* __restrict__ kb, int kstride, int kofs,
    const float* __restrict__ vb, int vstride, int vofs,
    float* __restrict__ ob, int dil)
{
    int warp = threadIdx.x >> 5, lane = threadIdx.x & 31;
    int pos = (blockIdx.x << 3) + warp;
    int b = pos >> 12, hw = pos & 4095, h = hw >> 6, x = hw & 63;

    float q0 = qb[(size_t)pos * QKVC + qofs + lane];
    float q1 = qb[(size_t)pos * QKVC + qofs + lane + 32];

    float logits[9];
    #pragma unroll
    for (int kk = 0; kk < 9; kk++) {
        int y = h + (kk / 3 - 1) * dil;
        int xx = x + (kk % 3 - 1) * dil;
        float p = 0.f;
        if (y >= 0 && y < H_ && xx >= 0 && xx < W_) {
            const float* kp = kb + (size_t)((b << 12) + (y << 6) + xx) * kstride + kofs;
            p = q0 * kp[lane] + q1 * kp[lane + 32];
        }
        #pragma unroll
        for (int s = 16; s; s >>= 1) p += __shfl_xor_sync(0xffffffffu, p, s);
        logits[kk] = p * 0.125f;
    }

    float mx = logits[0];
    #pragma unroll
    for (int kk = 1; kk < 9; kk++) mx = fmaxf(mx, logits[kk]);
    float e[9], den = 0.f;
    #pragma unroll
    for (int kk = 0; kk < 9; kk++) { e[kk] = expf(logits[kk] - mx); den += e[kk]; }
    float inv = 1.f / den;

    float o0 = 0.f, o1 = 0.f;
    #pragma unroll
    for (int kk = 0; kk < 9; kk++) {
        int y = h + (kk / 3 - 1) * dil;
        int xx = x + (kk % 3 - 1) * dil;
        if (y >= 0 && y < H_ && xx >= 0 && xx < W_) {
            const float* vp = vb + (size_t)((b << 12) + (y << 6) + xx) * vstride + vofs;
            float a = e[kk] * inv;
            o0 += a * vp[lane];
            o1 += a * vp[lane + 32];
        }
    }
    ob[(size_t)pos * C_ + lane]      = o0;
    ob[(size_t)pos * C_ + lane + 32] = o1;
}

// ---------------------------------------------------------------------------
// Launch
// ---------------------------------------------------------------------------
extern "C" void kernel_launch(void* const* d_in, const int* in_sizes, int n_in,
                              void* d_out, int out_size)
{
    const float* x      = (const float*)d_in[0];
    const float* qkv_w  = (const float*)d_in[1];
    const float* proj_w = (const float*)d_in[2];
    const float* proj_b = (const float*)d_in[3];
    const float* off_w2 = (const float*)d_in[4];
    const float* off_b2 = (const float*)d_in[5];
    const float* def_w2 = (const float*)d_in[6];
    const float* def_b2 = (const float*)d_in[7];
    const float* off_w3 = (const float*)d_in[8];
    const float* off_b3 = (const float*)d_in[9];
    const float* def_w3 = (const float*)d_in[10];
    const float* def_b3 = (const float*)d_in[11];
    float* out = (float*)d_out;

    float *p_qkv, *p_off, *p_sk, *p_sv, *p_dk2, *p_dv2, *p_dk3, *p_dv3, *p_attn, *p_wt;
    cudaGetSymbolAddress((void**)&p_qkv,  g_qkv);
    cudaGetSymbolAddress((void**)&p_off,  g_off);
    cudaGetSymbolAddress((void**)&p_sk,   g_sampk);
    cudaGetSymbolAddress((void**)&p_sv,   g_sampv);
    cudaGetSymbolAddress((void**)&p_dk2,  g_defk2);
    cudaGetSymbolAddress((void**)&p_dv2,  g_defv2);
    cudaGetSymbolAddress((void**)&p_dk3,  g_defk3);
    cudaGetSymbolAddress((void**)&p_dv3,  g_defv3);
    cudaGetSymbolAddress((void**)&p_attn, g_attn);
    cudaGetSymbolAddress((void**)&p_wt,   g_defWt);

    // 1) qkv = x @ qkv_w^T   [32768 x 192] x [576 x 192]^T
    mma_nt<<<dim3(QKVC / BN, M_ / BM), 128>>>(x, qkv_w, nullptr, p_qkv, QKVC, C_);

    // 2) deformable branches (dil = 2, 3)
    struct Br { int dil; const float *ow, *ob, *dw, *db; float *dk, *dv; };
    Br br[2] = {
        {2, off_w2, off_b2, def_w2, def_b2, p_dk2, p_dv2},
        {3, off_w3, off_b3, def_w3, def_b3, p_dk3, p_dv3},
    };
    for (int t = 0; t < 2; t++) {
        int i = t + 1;
        int kbase = 192 + i * 64;
        off_conv<<<M_ / 128, 128>>>(p_qkv, kbase, br[t].ow, br[t].ob, p_off, br[t].dil);
        wtrans<<<(64 * 576 + 255) / 256, 256>>>(br[t].dw, p_wt);
        sample_kv<<<M_, 288>>>(p_qkv, kbase, p_off, p_sk, p_sv, br[t].dil);
        mma_nt<<<dim3(1, M_ / BM), 128>>>(p_sk, p_wt, br[t].db, br[t].dk, HD, QKVC);
        mma_nt<<<dim3(1, M_ / BM), 128>>>(p_sv, p_wt, br[t].db, br[t].dv, HD, QKVC);
    }

    // 3) attention per branch -> g_attn [pos][branch*64+c]
    attn_kernel<<<M_ / 8, 256>>>(p_qkv, 0,   p_qkv, QKVC, 192, p_qkv, QKVC, 384, p_attn,       1);
    attn_kernel<<<M_ / 8, 256>>>(p_qkv, 64,  p_dk2, HD,   0,   p_dv2, HD,   0,   p_attn + 64,  2);
    attn_kernel<<<M_ / 8, 256>>>(p_qkv, 128, p_dk3, HD,   0,   p_dv3, HD,   0,   p_attn + 128, 3);

    // 4) out = attn @ proj_w^T + proj_b
    mma_nt<<<dim3(C_ / BN, M_ / BM), 128>>>(p_attn, proj_w, proj_b, out, C_, C_);
}

// round 4
// speedup vs baseline: 2.7608x; 1.6143x over previous
#include <cuda_runtime.h>
#include <math.h>

#define B_   8
#define H_   64
#define W_   64
#define HW_  4096
#define M_   32768
#define C_   192
#define QKVC 576
#define HD   64

// ---------------------------------------------------------------------------
// Scratch (static device globals)
// ---------------------------------------------------------------------------
__device__ float g_qkv[M_ * QKVC];      // [pos][576]  (q0..2 | k0..2 | v0..2)
__device__ float g_off[M_ * 18];
__device__ float g_Gk[M_ * QKVC];       // [pos][kk*64+o]
__device__ float g_Gv[M_ * QKVC];
__device__ float g_defk2[M_ * HD];
__device__ float g_defv2[M_ * HD];
__device__ float g_defk3[M_ * HD];
__device__ float g_defv3[M_ * HD];
__device__ float g_attn[M_ * C_];       // [pos][branch*64+c]
__device__ float g_W2[QKVC * HD];       // [kk*64+o][c]

// ---------------------------------------------------------------------------
// tf32 helpers
// ---------------------------------------------------------------------------
__device__ __forceinline__ unsigned f2tf32(float f) {
    unsigned u;
    asm("cvt.rna.tf32.f32 %0, %1;" : "=r"(u) : "f"(f));
    return u;
}

__device__ __forceinline__ void mma_tf32(float (&d)[4], const unsigned (&a)[4],
                                         const unsigned (&b)[2]) {
    asm volatile(
        "mma.sync.aligned.m16n8k8.row.col.f32.tf32.tf32.f32 "
        "{%0,%1,%2,%3}, {%4,%5,%6,%7}, {%8,%9}, {%0,%1,%2,%3};\n"
        : "+f"(d[0]), "+f"(d[1]), "+f"(d[2]), "+f"(d[3])
        : "r"(a[0]), "r"(a[1]), "r"(a[2]), "r"(a[3]), "r"(b[0]), "r"(b[1]));
}

// ---------------------------------------------------------------------------
// Tensor-core NT GEMM (tf32): C[m,n] = sum_k A[m,k] * Wt[n,k] (+ bias[n])
// Block tile 128x64, 4 warps, warp tile 64x32, BK=16, double-buffered.
// A row stride = lda, Wt row stride = ldb, C row stride = N (packed).
// ---------------------------------------------------------------------------
#define BM 128
#define BN 64
#define BK 16
#define PAD 20

__global__ __launch_bounds__(128) void mma_nt(
    const float* __restrict__ A, int lda,
    const float* __restrict__ Wt, int ldb,
    const float* __restrict__ bias, float* __restrict__ C,
    int N, int Kd)
{
    __shared__ __align__(16) unsigned As[2][BM * PAD];
    __shared__ __align__(16) unsigned Bs[2][BN * PAD];

    const int tid  = threadIdx.x;
    const int lane = tid & 31;
    const int warp = tid >> 5;
    const int wm = warp >> 1, wn = warp & 1;
    const int g = lane >> 2, t = lane & 3;
    const int m0 = blockIdx.y * BM;
    const int n0 = blockIdx.x * BN;

    float acc[4][4][4] = {};
    const int nit = Kd / BK;
    float4 ra[4], rb[2];

    #pragma unroll
    for (int i = 0; i < 4; i++) {
        int f = tid + i * 128, row = f >> 2, kq = f & 3;
        ra[i] = *reinterpret_cast<const float4*>(&A[(size_t)(m0 + row) * lda + kq * 4]);
    }
    #pragma unroll
    for (int i = 0; i < 2; i++) {
        int f = tid + i * 128, row = f >> 2, kq = f & 3;
        rb[i] = *reinterpret_cast<const float4*>(&Wt[(size_t)(n0 + row) * ldb + kq * 4]);
    }
    #pragma unroll
    for (int i = 0; i < 4; i++) {
        int f = tid + i * 128, row = f >> 2, kq = f & 3;
        unsigned* p = &As[0][row * PAD + kq * 4];
        p[0] = f2tf32(ra[i].x); p[1] = f2tf32(ra[i].y);
        p[2] = f2tf32(ra[i].z); p[3] = f2tf32(ra[i].w);
    }
    #pragma unroll
    for (int i = 0; i < 2; i++) {
        int f = tid + i * 128, row = f >> 2, kq = f & 3;
        unsigned* p = &Bs[0][row * PAD + kq * 4];
        p[0] = f2tf32(rb[i].x); p[1] = f2tf32(rb[i].y);
        p[2] = f2tf32(rb[i].z); p[3] = f2tf32(rb[i].w);
    }
    __syncthreads();

    for (int it = 0; it < nit; it++) {
        const int buf = it & 1;
        const bool more = (it + 1) < nit;
        if (more) {
            int k0 = (it + 1) * BK;
            #pragma unroll
            for (int i = 0; i < 4; i++) {
                int f = tid + i * 128, row = f >> 2, kq = f & 3;
                ra[i] = *reinterpret_cast<const float4*>(&A[(size_t)(m0 + row) * lda + k0 + kq * 4]);
            }
            #pragma unroll
            for (int i = 0; i < 2; i++) {
                int f = tid + i * 128, row = f >> 2, kq = f & 3;
                rb[i] = *reinterpret_cast<const float4*>(&Wt[(size_t)(n0 + row) * ldb + k0 + kq * 4]);
            }
        }

        #pragma unroll
        for (int ks = 0; ks < 16; ks += 8) {
            unsigned af[4][4], bf[4][2];
            #pragma unroll
            for (int mi = 0; mi < 4; mi++) {
                int r = wm * 64 + mi * 16 + g;
                af[mi][0] = As[buf][r * PAD + ks + t];
                af[mi][1] = As[buf][(r + 8) * PAD + ks + t];
                af[mi][2] = As[buf][r * PAD + ks + t + 4];
                af[mi][3] = As[buf][(r + 8) * PAD + ks + t + 4];
            }
            #pragma unroll
            for (int nj = 0; nj < 4; nj++) {
                int cc = wn * 32 + nj * 8 + g;
                bf[nj][0] = Bs[buf][cc * PAD + ks + t];
                bf[nj][1] = Bs[buf][cc * PAD + ks + t + 4];
            }
            #pragma unroll
            for (int mi = 0; mi < 4; mi++)
                #pragma unroll
                for (int nj = 0; nj < 4; nj++)
                    mma_tf32(acc[mi][nj], af[mi], bf[nj]);
        }

        if (more) {
            const int nb = (it + 1) & 1;
            #pragma unroll
            for (int i = 0; i < 4; i++) {
                int f = tid + i * 128, row = f >> 2, kq = f & 3;
                unsigned* p = &As[nb][row * PAD + kq * 4];
                p[0] = f2tf32(ra[i].x); p[1] = f2tf32(ra[i].y);
                p[2] = f2tf32(ra[i].z); p[3] = f2tf32(ra[i].w);
            }
            #pragma unroll
            for (int i = 0; i < 2; i++) {
                int f = tid + i * 128, row = f >> 2, kq = f & 3;
                unsigned* p = &Bs[nb][row * PAD + kq * 4];
                p[0] = f2tf32(rb[i].x); p[1] = f2tf32(rb[i].y);
                p[2] = f2tf32(rb[i].z); p[3] = f2tf32(rb[i].w);
            }
            __syncthreads();
        }
    }

    #pragma unroll
    for (int mi = 0; mi < 4; mi++) {
        int r = m0 + wm * 64 + mi * 16 + g;
        #pragma unroll
        for (int nj = 0; nj < 4; nj++) {
            int c = n0 + wn * 32 + nj * 8 + 2 * t;
            float b0 = bias ? bias[c] : 0.f;
            float b1 = bias ? bias[c + 1] : 0.f;
            float2 lo = make_float2(acc[mi][nj][0] + b0, acc[mi][nj][1] + b1);
            float2 hi = make_float2(acc[mi][nj][2] + b0, acc[mi][nj][3] + b1);
            *reinterpret_cast<float2*>(&C[(size_t)r * N + c]) = lo;
            *reinterpret_cast<float2*>(&C[(size_t)(r + 8) * N + c]) = hi;
        }
    }
}

// ---------------------------------------------------------------------------
// Dilated 3x3 conv producing 18 offset channels. One thread per position.
// ---------------------------------------------------------------------------
__global__ __launch_bounds__(256) void off_conv(
    const float* __restrict__ qkv, int kbase,
    const float* __restrict__ wgt, const float* __restrict__ bias,
    float* __restrict__ out, int dil)
{
    __shared__ float ws[18 * 576];
    for (int i = threadIdx.x; i < 18 * 576; i += blockDim.x) ws[i] = wgt[i];
    __syncthreads();

    int pos = blockIdx.x * blockDim.x + threadIdx.x;
    int b = pos >> 12, hw = pos & 4095, h = hw >> 6, x = hw & 63;

    float acc[18];
    #pragma unroll
    for (int o = 0; o < 18; o++) acc[o] = bias[o];

    for (int ky = 0; ky < 3; ky++) {
        int y = h + (ky - 1) * dil;
        if (y < 0 || y >= H_) continue;
        for (int kx = 0; kx < 3; kx++) {
            int xx = x + (kx - 1) * dil;
            if (xx < 0 || xx >= W_) continue;
            const float* kp = qkv + (size_t)((b << 12) + (y << 6) + xx) * QKVC + kbase;
            int kkk = ky * 3 + kx;
            for (int c = 0; c < 64; c++) {
                float kv = kp[c];
                const float* wp = &ws[c * 9 + kkk];
                #pragma unroll
                for (int o = 0; o < 18; o++) acc[o] += kv * wp[o * 576];
            }
        }
    }
    float* op = out + (size_t)pos * 18;
    #pragma unroll
    for (int o = 0; o < 18; o++) op[o] = acc[o];
}

// ---------------------------------------------------------------------------
// def_w (64,64,3,3) [o][c][kk] -> W2[kk*64+o][c]
// ---------------------------------------------------------------------------
__global__ void wtrans2(const float* __restrict__ w, float* __restrict__ wt)
{
    int i = blockIdx.x * blockDim.x + threadIdx.x;
    if (i >= 64 * 576) return;
    int o = i / 576, r = i % 576, c = r / 9, kk = r % 9;
    wt[(kk * 64 + o) * 64 + c] = w[i];
}

// ---------------------------------------------------------------------------
// Deformable gather: defk[pos][o] = db[o] + sum_kk sum_corner w * Gk[corner][kk*64+o]
// One warp per position. Lanes 0..8 precompute per-tap corner indices +
// masked weights; broadcast via shfl. lane: arr = lane>>4 (k|v), 4 channels.
// ---------------------------------------------------------------------------
__global__ __launch_bounds__(256) void deform_gather(
    const float* __restrict__ Gk, const float* __restrict__ Gv,
    const float* __restrict__ off, const float* __restrict__ bias,
    float* __restrict__ dk, float* __restrict__ dv, int dil)
{
    const int warp = threadIdx.x >> 5, lane = threadIdx.x & 31;
    const int pos = (blockIdx.x << 3) + warp;
    const int b = pos >> 12, hw = pos & 4095, h = hw >> 6, x = hw & 63;

    // lanes 0..8: compute tap data
    int kk = lane;
    float offy = 0.f, offx = 0.f;
    if (kk < 9) {
        offy = off[pos * 18 + 2 * kk];
        offx = off[pos * 18 + 2 * kk + 1];
    }
    float py = (float)h + (float)((kk / 3) * dil - dil) + offy;
    float px = (float)x + (float)((kk % 3) * dil - dil) + offx;
    float y0f = floorf(py), x0f = floorf(px);
    float wy = py - y0f, wx = px - x0f;
    int y0 = (int)y0f, x0 = (int)x0f, y1 = y0 + 1, x1 = x0 + 1;
    float fy0 = (float)(y0 >= 0 && y0 < H_);
    float fy1 = (float)(y1 >= 0 && y1 < H_);
    float fx0 = (float)(x0 >= 0 && x0 < W_);
    float fx1 = (float)(x1 >= 0 && x1 < W_);
    float w00 = (1.f - wy) * (1.f - wx) * fy0 * fx0;
    float w01 = (1.f - wy) * wx        * fy0 * fx1;
    float w10 = wy * (1.f - wx)        * fy1 * fx0;
    float w11 = wy * wx                * fy1 * fx1;
    int y0c = min(max(y0, 0), H_ - 1), y1c = min(max(y1, 0), H_ - 1);
    int x0c = min(max(x0, 0), W_ - 1), x1c = min(max(x1, 0), W_ - 1);
    int rbase = b << 12;
    int tapofs = kk * 64;
    int i00 = (rbase + (y0c << 6) + x0c) * QKVC + tapofs;
    int i01 = (rbase + (y0c << 6) + x1c) * QKVC + tapofs;
    int i10 = (rbase + (y1c << 6) + x0c) * QKVC + tapofs;
    int i11 = (rbase + (y1c << 6) + x1c) * QKVC + tapofs;

    const int arr = lane >> 4;          // 0 = k, 1 = v
    const int c4 = (lane & 15) * 4;
    const float* __restrict__ G = arr ? Gv : Gk;

    float4 bv = *reinterpret_cast<const float4*>(&bias[c4]);
    float4 acc = bv;

    #pragma unroll
    for (int t = 0; t < 9; t++) {
        float a00 = __shfl_sync(0xffffffffu, w00, t);
        float a01 = __shfl_sync(0xffffffffu, w01, t);
        float a10 = __shfl_sync(0xffffffffu, w10, t);
        float a11 = __shfl_sync(0xffffffffu, w11, t);
        int   j00 = __shfl_sync(0xffffffffu, i00, t);
        int   j01 = __shfl_sync(0xffffffffu, i01, t);
        int   j10 = __shfl_sync(0xffffffffu, i10, t);
        int   j11 = __shfl_sync(0xffffffffu, i11, t);
        float4 u;
        u = *reinterpret_cast<const float4*>(&G[j00 + c4]);
        acc.x += a00 * u.x; acc.y += a00 * u.y; acc.z += a00 * u.z; acc.w += a00 * u.w;
        u = *reinterpret_cast<const float4*>(&G[j01 + c4]);
        acc.x += a01 * u.x; acc.y += a01 * u.y; acc.z += a01 * u.z; acc.w += a01 * u.w;
        u = *reinterpret_cast<const float4*>(&G[j10 + c4]);
        acc.x += a10 * u.x; acc.y += a10 * u.y; acc.z += a10 * u.z; acc.w += a10 * u.w;
        u = *reinterpret_cast<const float4*>(&G[j11 + c4]);
        acc.x += a11 * u.x; acc.y += a11 * u.y; acc.z += a11 * u.z; acc.w += a11 * u.w;
    }

    float* __restrict__ dst = arr ? dv : dk;
    *reinterpret_cast<float4*>(&dst[pos * HD + c4]) = acc;
}

// ---------------------------------------------------------------------------
// 9-tap local attention, all 3 branches in one launch (blockIdx.y = branch).
// One warp per position; lane covers channels lane, lane+32.
// ---------------------------------------------------------------------------
__global__ __launch_bounds__(256) void attn_all(
    const float* __restrict__ qkv,
    const float* __restrict__ dk2, const float* __restrict__ dv2,
    const float* __restrict__ dk3, const float* __restrict__ dv3,
    float* __restrict__ ob)
{
    const int br = blockIdx.y;
    const int warp = threadIdx.x >> 5, lane = threadIdx.x & 31;
    const int pos = (blockIdx.x << 3) + warp;
    const int b = pos >> 12, hw = pos & 4095, h = hw >> 6, x = hw & 63;

    const float* kb; const float* vb; int kstride, kofs, vofs, dil;
    if (br == 0)      { kb = qkv; vb = qkv; kstride = QKVC; kofs = 192; vofs = 384; dil = 1; }
    else if (br == 1) { kb = dk2; vb = dv2; kstride = HD;   kofs = 0;   vofs = 0;   dil = 2; }
    else              { kb = dk3; vb = dv3; kstride = HD;   kofs = 0;   vofs = 0;   dil = 3; }

    const int qofs = br * 64;
    float q0 = qkv[pos * QKVC + qofs + lane];
    float q1 = qkv[pos * QKVC + qofs + lane + 32];

    float logits[9];
    #pragma unroll
    for (int kk = 0; kk < 9; kk++) {
        int y = h + (kk / 3 - 1) * dil;
        int xx = x + (kk % 3 - 1) * dil;
        float p = 0.f;
        if (y >= 0 && y < H_ && xx >= 0 && xx < W_) {
            const float* kp = kb + ((b << 12) + (y << 6) + xx) * kstride + kofs;
            p = q0 * kp[lane] + q1 * kp[lane + 32];
        }
        #pragma unroll
        for (int s = 16; s; s >>= 1) p += __shfl_xor_sync(0xffffffffu, p, s);
        logits[kk] = p * 0.125f;
    }

    float mx = logits[0];
    #pragma unroll
    for (int kk = 1; kk < 9; kk++) mx = fmaxf(mx, logits[kk]);
    float e[9], den = 0.f;
    #pragma unroll
    for (int kk = 0; kk < 9; kk++) { e[kk] = __expf(logits[kk] - mx); den += e[kk]; }
    float inv = 1.f / den;

    float o0 = 0.f, o1 = 0.f;
    #pragma unroll
    for (int kk = 0; kk < 9; kk++) {
        int y = h + (kk / 3 - 1) * dil;
        int xx = x + (kk % 3 - 1) * dil;
        if (y >= 0 && y < H_ && xx >= 0 && xx < W_) {
            const float* vp = vb + ((b << 12) + (y << 6) + xx) * kstride + vofs;
            float a = e[kk] * inv;
            o0 += a * vp[lane];
            o1 += a * vp[lane + 32];
        }
    }
    ob[pos * C_ + qofs + lane]      = o0;
    ob[pos * C_ + qofs + lane + 32] = o1;
}

// ---------------------------------------------------------------------------
// Launch
// ---------------------------------------------------------------------------
extern "C" void kernel_launch(void* const* d_in, const int* in_sizes, int n_in,
                              void* d_out, int out_size)
{
    const float* x      = (const float*)d_in[0];
    const float* qkv_w  = (const float*)d_in[1];
    const float* proj_w = (const float*)d_in[2];
    const float* proj_b = (const float*)d_in[3];
    const float* off_w2 = (const float*)d_in[4];
    const float* off_b2 = (const float*)d_in[5];
    const float* def_w2 = (const float*)d_in[6];
    const float* def_b2 = (const float*)d_in[7];
    const float* off_w3 = (const float*)d_in[8];
    const float* off_b3 = (const float*)d_in[9];
    const float* def_w3 = (const float*)d_in[10];
    const float* def_b3 = (const float*)d_in[11];
    float* out = (float*)d_out;

    float *p_qkv, *p_off, *p_gk, *p_gv, *p_dk2, *p_dv2, *p_dk3, *p_dv3, *p_attn, *p_w2;
    cudaGetSymbolAddress((void**)&p_qkv,  g_qkv);
    cudaGetSymbolAddress((void**)&p_off,  g_off);
    cudaGetSymbolAddress((void**)&p_gk,   g_Gk);
    cudaGetSymbolAddress((void**)&p_gv,   g_Gv);
    cudaGetSymbolAddress((void**)&p_dk2,  g_defk2);
    cudaGetSymbolAddress((void**)&p_dv2,  g_defv2);
    cudaGetSymbolAddress((void**)&p_dk3,  g_defk3);
    cudaGetSymbolAddress((void**)&p_dv3,  g_defv3);
    cudaGetSymbolAddress((void**)&p_attn, g_attn);
    cudaGetSymbolAddress((void**)&p_w2,   g_W2);

    // 1) qkv = x @ qkv_w^T
    mma_nt<<<dim3(QKVC / BN, M_ / BM), 128>>>(x, C_, qkv_w, C_, nullptr, p_qkv, QKVC, C_);

    // 2) deformable branches (dil = 2, 3)
    struct Br { int dil; const float *ow, *ob, *dw, *db; float *dk, *dv; };
    Br br[2] = {
        {2, off_w2, off_b2, def_w2, def_b2, p_dk2, p_dv2},
        {3, off_w3, off_b3, def_w3, def_b3, p_dk3, p_dv3},
    };
    for (int t = 0; t < 2; t++) {
        int kbase = 192 + (t + 1) * 64;
        int vbase = 384 + (t + 1) * 64;
        off_conv<<<M_ / 256, 256>>>(p_qkv, kbase, br[t].ow, br[t].ob, p_off, br[t].dil);
        wtrans2<<<(64 * 576 + 255) / 256, 256>>>(br[t].dw, p_w2);
        mma_nt<<<dim3(QKVC / BN, M_ / BM), 128>>>(p_qkv + kbase, QKVC, p_w2, HD, nullptr, p_gk, QKVC, HD);
        mma_nt<<<dim3(QKVC / BN, M_ / BM), 128>>>(p_qkv + vbase, QKVC, p_w2, HD, nullptr, p_gv, QKVC, HD);
        deform_gather<<<M_ / 8, 256>>>(p_gk, p_gv, p_off, br[t].db, br[t].dk, br[t].dv, br[t].dil);
    }

    // 3) attention, all branches
    attn_all<<<dim3(M_ / 8, 3), 256>>>(p_qkv, p_dk2, p_dv2, p_dk3, p_dv3, p_attn);

    // 4) out = attn @ proj_w^T + proj_b
    mma_nt<<<dim3(C_ / BN, M_ / BM), 128>>>(p_attn, C_, proj_w, C_, proj_b, out, C_, C_);
}

// round 5
// speedup vs baseline: 3.9534x; 1.4320x over previous
#include <cuda_runtime.h>
#include <math.h>

#define B_   8
#define H_   64
#define W_   64
#define M_   32768
#define C_   192
#define QKVC 576
#define HD   64
#define GN   768   // G row stride: 576 (Gk/Gv) + 162 (OffG) + pad

// ---------------------------------------------------------------------------
// Scratch (static device globals)
// ---------------------------------------------------------------------------
__device__ float g_qkv[M_ * QKVC];       // [pos][576]
__device__ float g_G[4][M_ * GN];        // z = {k2, v2, k3, v3}
__device__ float g_defk2[M_ * HD];
__device__ float g_defv2[M_ * HD];
__device__ float g_defk3[M_ * HD];
__device__ float g_defv3[M_ * HD];
__device__ float g_attn[M_ * C_];        // [pos][branch*64+c]
__device__ float g_Wc[2][GN * HD];       // combined [def | off] weights per branch

// ---------------------------------------------------------------------------
// tf32 helpers
// ---------------------------------------------------------------------------
__device__ __forceinline__ unsigned f2tf32(float f) {
    unsigned u;
    asm("cvt.rna.tf32.f32 %0, %1;" : "=r"(u) : "f"(f));
    return u;
}

__device__ __forceinline__ void mma_tf32(float (&d)[4], const unsigned (&a)[4],
                                         const unsigned (&b)[2]) {
    asm volatile(
        "mma.sync.aligned.m16n8k8.row.col.f32.tf32.tf32.f32 "
        "{%0,%1,%2,%3}, {%4,%5,%6,%7}, {%8,%9}, {%0,%1,%2,%3};\n"
        : "+f"(d[0]), "+f"(d[1]), "+f"(d[2]), "+f"(d[3])
        : "r"(a[0]), "r"(a[1]), "r"(a[2]), "r"(a[3]), "r"(b[0]), "r"(b[1]));
}

// ---------------------------------------------------------------------------
// tf32 NT GEMM core. Block 128x64, 4 warps, warp tile 64x32, BK=16, double
// buffered. Smem k-interleaved within 8-k blocks: word = (k>>3)*8 +
// (k&3)*2 + ((k>>2)&1), so fragment pairs (t, t+4) are adjacent -> LDS.64.
// ---------------------------------------------------------------------------
#define BM 128
#define BN 64
#define BK 16
#define PAD 20

__device__ __forceinline__ void gemm_core(
    const float* __restrict__ A, int lda,
    const float* __restrict__ Wt, int ldb,
    const float* __restrict__ bias, float* __restrict__ C, int ldc,
    int m0, int n0, int Kd, unsigned* As, unsigned* Bs)
{
    const int tid  = threadIdx.x;
    const int lane = tid & 31;
    const int warp = tid >> 5;
    const int wm = warp >> 1, wn = warp & 1;
    const int g = lane >> 2, t = lane & 3;
    const int lrow = tid >> 2, lkq = tid & 3;
    const int spos = ((lkq >> 1) << 3) + (lkq & 1);   // + j*2 for j-th value

    float acc[4][4][4] = {};
    const int nit = Kd / BK;
    float4 ra[4], rb[2];

    // prefetch iter 0
    #pragma unroll
    for (int i = 0; i < 4; i++)
        ra[i] = *reinterpret_cast<const float4*>(&A[(size_t)(m0 + lrow + 32 * i) * lda + lkq * 4]);
    #pragma unroll
    for (int i = 0; i < 2; i++)
        rb[i] = *reinterpret_cast<const float4*>(&Wt[(size_t)(n0 + lrow + 32 * i) * ldb + lkq * 4]);
    #pragma unroll
    for (int i = 0; i < 4; i++) {
        unsigned* p = &As[(lrow + 32 * i) * PAD + spos];
        p[0] = f2tf32(ra[i].x); p[2] = f2tf32(ra[i].y);
        p[4] = f2tf32(ra[i].z); p[6] = f2tf32(ra[i].w);
    }
    #pragma unroll
    for (int i = 0; i < 2; i++) {
        unsigned* p = &Bs[(lrow + 32 * i) * PAD + spos];
        p[0] = f2tf32(rb[i].x); p[2] = f2tf32(rb[i].y);
        p[4] = f2tf32(rb[i].z); p[6] = f2tf32(rb[i].w);
    }
    __syncthreads();

    for (int it = 0; it < nit; it++) {
        const int buf = it & 1;
        const bool more = (it + 1) < nit;
        const unsigned* pa = &As[buf * BM * PAD];
        const unsigned* pb = &Bs[buf * BN * PAD];

        if (more) {
            int k0 = (it + 1) * BK;
            #pragma unroll
            for (int i = 0; i < 4; i++)
                ra[i] = *reinterpret_cast<const float4*>(&A[(size_t)(m0 + lrow + 32 * i) * lda + k0 + lkq * 4]);
            #pragma unroll
            for (int i = 0; i < 2; i++)
                rb[i] = *reinterpret_cast<const float4*>(&Wt[(size_t)(n0 + lrow + 32 * i) * ldb + k0 + lkq * 4]);
        }

        #pragma unroll
        for (int ks = 0; ks < 2; ks++) {
            unsigned af[4][4], bf[4][2];
            #pragma unroll
            for (int mi = 0; mi < 4; mi++) {
                int r = wm * 64 + mi * 16 + g;
                uint2 u0 = *reinterpret_cast<const uint2*>(&pa[r * PAD + ks * 8 + t * 2]);
                uint2 u1 = *reinterpret_cast<const uint2*>(&pa[(r + 8) * PAD + ks * 8 + t * 2]);
                af[mi][0] = u0.x; af[mi][1] = u1.x; af[mi][2] = u0.y; af[mi][3] = u1.y;
            }
            #pragma unroll
            for (int nj = 0; nj < 4; nj++) {
                int cc = wn * 32 + nj * 8 + g;
                uint2 ub = *reinterpret_cast<const uint2*>(&pb[cc * PAD + ks * 8 + t * 2]);
                bf[nj][0] = ub.x; bf[nj][1] = ub.y;
            }
            #pragma unroll
            for (int mi = 0; mi < 4; mi++)
                #pragma unroll
                for (int nj = 0; nj < 4; nj++)
                    mma_tf32(acc[mi][nj], af[mi], bf[nj]);
        }

        if (more) {
            const int nb = (it + 1) & 1;
            #pragma unroll
            for (int i = 0; i < 4; i++) {
                unsigned* p = &As[nb * BM * PAD + (lrow + 32 * i) * PAD + spos];
                p[0] = f2tf32(ra[i].x); p[2] = f2tf32(ra[i].y);
                p[4] = f2tf32(ra[i].z); p[6] = f2tf32(ra[i].w);
            }
            #pragma unroll
            for (int i = 0; i < 2; i++) {
                unsigned* p = &Bs[nb * BN * PAD + (lrow + 32 * i) * PAD + spos];
                p[0] = f2tf32(rb[i].x); p[2] = f2tf32(rb[i].y);
                p[4] = f2tf32(rb[i].z); p[6] = f2tf32(rb[i].w);
            }
            __syncthreads();
        }
    }

    #pragma unroll
    for (int mi = 0; mi < 4; mi++) {
        int r = m0 + wm * 64 + mi * 16 + g;
        #pragma unroll
        for (int nj = 0; nj < 4; nj++) {
            int c = n0 + wn * 32 + nj * 8 + 2 * t;
            float b0 = bias ? bias[c] : 0.f;
            float b1 = bias ? bias[c + 1] : 0.f;
            float2 lo = make_float2(acc[mi][nj][0] + b0, acc[mi][nj][1] + b1);
            float2 hi = make_float2(acc[mi][nj][2] + b0, acc[mi][nj][3] + b1);
            *reinterpret_cast<float2*>(&C[(size_t)r * ldc + c]) = lo;
            *reinterpret_cast<float2*>(&C[(size_t)(r + 8) * ldc + c]) = hi;
        }
    }
}

__global__ __launch_bounds__(128) void mma_nt(
    const float* __restrict__ A, int lda,
    const float* __restrict__ Wt, int ldb,
    const float* __restrict__ bias, float* __restrict__ C,
    int ldc, int Kd)
{
    __shared__ __align__(16) unsigned As[2 * BM * PAD];
    __shared__ __align__(16) unsigned Bs[2 * BN * PAD];
    gemm_core(A, lda, Wt, ldb, bias, C, ldc,
              blockIdx.y * BM, blockIdx.x * BN, Kd, As, Bs);
}

// Merged G GEMMs: z = {k2, v2, k3, v3}. A = qkv slice [M x 64], lda = 576.
// W = g_Wc[branch] [768 x 64]. Out = g_G[z] [M x 768]. K=64.
// v slices (z odd) skip the OffG columns (n0 >= 576).
__global__ __launch_bounds__(128) void mma_g(
    const float* __restrict__ qkv, const float* __restrict__ Wc,
    float* __restrict__ G)
{
    const int z = blockIdx.z;
    const int n0 = blockIdx.x * BN;
    if ((z & 1) && n0 >= QKVC) return;
    __shared__ __align__(16) unsigned As[2 * BM * PAD];
    __shared__ __align__(16) unsigned Bs[2 * BN * PAD];
    const int ofsA = 256 + (z >> 1) * 64 + (z & 1) * 192;
    gemm_core(qkv + ofsA, QKVC, Wc + (size_t)(z >> 1) * GN * HD, HD, nullptr,
              G + (size_t)z * M_ * GN, GN, blockIdx.y * BM, n0, HD, As, Bs);
}

// ---------------------------------------------------------------------------
// Build combined weights: rows 0..575: W2[kk*64+o][c] = def_w[o][c][kk]
//                         rows 576..737: Woff2[kk*18+o][c] = off_w[o][c][kk]
//                         rows 738..767: zero
// ---------------------------------------------------------------------------
__global__ void build_w(const float* __restrict__ dw2, const float* __restrict__ ow2,
                        const float* __restrict__ dw3, const float* __restrict__ ow3,
                        float* __restrict__ Wc)
{
    int i = blockIdx.x * blockDim.x + threadIdx.x;
    if (i >= 2 * GN * HD) return;
    int br = i / (GN * HD);
    int r  = (i / HD) % GN;
    int c  = i % HD;
    const float* dw = br ? dw3 : dw2;
    const float* ow = br ? ow3 : ow2;
    float v = 0.f;
    if (r < QKVC) {
        int kk = r >> 6, o = r & 63;
        v = dw[o * 576 + c * 9 + kk];
    } else if (r < QKVC + 162) {
        int rr = r - QKVC, kk = rr / 18, o = rr % 18;
        v = ow[o * 576 + c * 9 + kk];
    }
    Wc[i] = v;
}

// ---------------------------------------------------------------------------
// Deformable gather, both branches (blockIdx.y). One warp per position.
// Phase 1: lanes 0..17 compute offsets o=lane via integer 9-tap gather of
//          the OffG columns of Gk.
// Phase 2: lanes 0..8 compute per-tap bilinear corner indices + masked
//          weights; broadcast via shfl; all lanes accumulate k|v channels.
// ---------------------------------------------------------------------------
__global__ __launch_bounds__(256) void deform_gather(
    const float* __restrict__ G,
    const float* __restrict__ ob2, const float* __restrict__ db2,
    const float* __restrict__ ob3, const float* __restrict__ db3,
    float* __restrict__ dk2, float* __restrict__ dv2,
    float* __restrict__ dk3, float* __restrict__ dv3)
{
    const int br  = blockIdx.y;
    const int dil = br + 2;
    const float* __restrict__ Gk = G + (size_t)(2 * br) * M_ * GN;
    const float* __restrict__ Gv = G + (size_t)(2 * br + 1) * M_ * GN;
    const float* offb = br ? ob3 : ob2;
    const float* defb = br ? db3 : db2;
    float* dk = br ? dk3 : dk2;
    float* dv = br ? dv3 : dv2;

    const int warp = threadIdx.x >> 5, lane = threadIdx.x & 31;
    const int pos = (blockIdx.x << 3) + warp;
    const int b = pos >> 12, hw = pos & 4095, h = hw >> 6, x = hw & 63;
    const int rbase = b << 12;

    // Phase 1: offsets
    float offa = (lane < 18) ? offb[lane] : 0.f;
    #pragma unroll
    for (int kq = 0; kq < 9; kq++) {
        int y  = h + (kq / 3 - 1) * dil;
        int xx = x + (kq % 3 - 1) * dil;
        if (lane < 18 && y >= 0 && y < H_ && xx >= 0 && xx < W_)
            offa += Gk[(size_t)(rbase + (y << 6) + xx) * GN + QKVC + kq * 18 + lane];
    }

    // Phase 2: per-tap bilinear setup (lanes 0..8 meaningful)
    int kk = lane;
    float offy = __shfl_sync(0xffffffffu, offa, (2 * lane) & 31);
    float offx = __shfl_sync(0xffffffffu, offa, (2 * lane + 1) & 31);
    float py = (float)h + (float)((kk / 3) * dil - dil) + offy;
    float px = (float)x + (float)((kk % 3) * dil - dil) + offx;
    float y0f = floorf(py), x0f = floorf(px);
    float wy = py - y0f, wx = px - x0f;
    int y0 = (int)y0f, x0 = (int)x0f, y1 = y0 + 1, x1 = x0 + 1;
    float fy0 = (float)(y0 >= 0 && y0 < H_);
    float fy1 = (float)(y1 >= 0 && y1 < H_);
    float fx0 = (float)(x0 >= 0 && x0 < W_);
    float fx1 = (float)(x1 >= 0 && x1 < W_);
    float w00 = (1.f - wy) * (1.f - wx) * fy0 * fx0;
    float w01 = (1.f - wy) * wx        * fy0 * fx1;
    float w10 = wy * (1.f - wx)        * fy1 * fx0;
    float w11 = wy * wx                * fy1 * fx1;
    int y0c = min(max(y0, 0), H_ - 1), y1c = min(max(y1, 0), H_ - 1);
    int x0c = min(max(x0, 0), W_ - 1), x1c = min(max(x1, 0), W_ - 1);
    int tapofs = kk * 64;
    int i00 = (rbase + (y0c << 6) + x0c) * GN + tapofs;
    int i01 = (rbase + (y0c << 6) + x1c) * GN + tapofs;
    int i10 = (rbase + (y1c << 6) + x0c) * GN + tapofs;
    int i11 = (rbase + (y1c << 6) + x1c) * GN + tapofs;

    const int arr = lane >> 4;            // 0 = k, 1 = v
    const int c4 = (lane & 15) * 4;
    const float* __restrict__ Gs = arr ? Gv : Gk;

    float4 acc = *reinterpret_cast<const float4*>(&defb[c4]);

    #pragma unroll
    for (int tp = 0; tp < 9; tp++) {
        float a00 = __shfl_sync(0xffffffffu, w00, tp);
        float a01 = __shfl_sync(0xffffffffu, w01, tp);
        float a10 = __shfl_sync(0xffffffffu, w10, tp);
        float a11 = __shfl_sync(0xffffffffu, w11, tp);
        int   j00 = __shfl_sync(0xffffffffu, i00, tp);
        int   j01 = __shfl_sync(0xffffffffu, i01, tp);
        int   j10 = __shfl_sync(0xffffffffu, i10, tp);
        int   j11 = __shfl_sync(0xffffffffu, i11, tp);
        float4 u;
        u = *reinterpret_cast<const float4*>(&Gs[j00 + c4]);
        acc.x += a00 * u.x; acc.y += a00 * u.y; acc.z += a00 * u.z; acc.w += a00 * u.w;
        u = *reinterpret_cast<const float4*>(&Gs[j01 + c4]);
        acc.x += a01 * u.x; acc.y += a01 * u.y; acc.z += a01 * u.z; acc.w += a01 * u.w;
        u = *reinterpret_cast<const float4*>(&Gs[j10 + c4]);
        acc.x += a10 * u.x; acc.y += a10 * u.y; acc.z += a10 * u.z; acc.w += a10 * u.w;
        u = *reinterpret_cast<const float4*>(&Gs[j11 + c4]);
        acc.x += a11 * u.x; acc.y += a11 * u.y; acc.z += a11 * u.z; acc.w += a11 * u.w;
    }

    float* __restrict__ dst = arr ? dv : dk;
    *reinterpret_cast<float4*>(&dst[pos * HD + c4]) = acc;
}

// ---------------------------------------------------------------------------
// 9-tap local attention, all 3 branches (blockIdx.y). Warp per position.
// ---------------------------------------------------------------------------
__global__ __launch_bounds__(256) void attn_all(
    const float* __restrict__ qkv,
    const float* __restrict__ dk2, const float* __restrict__ dv2,
    const float* __restrict__ dk3, const float* __restrict__ dv3,
    float* __restrict__ ob)
{
    const int br = blockIdx.y;
    const int warp = threadIdx.x >> 5, lane = threadIdx.x & 31;
    const int pos = (blockIdx.x << 3) + warp;
    const int b = pos >> 12, hw = pos & 4095, h = hw >> 6, x = hw & 63;

    const float* kb; const float* vb; int kstride, kofs, vofs, dil;
    if (br == 0)      { kb = qkv; vb = qkv; kstride = QKVC; kofs = 192; vofs = 384; dil = 1; }
    else if (br == 1) { kb = dk2; vb = dv2; kstride = HD;   kofs = 0;   vofs = 0;   dil = 2; }
    else              { kb = dk3; vb = dv3; kstride = HD;   kofs = 0;   vofs = 0;   dil = 3; }

    const int qofs = br * 64;
    float q0 = qkv[pos * QKVC + qofs + lane];
    float q1 = qkv[pos * QKVC + qofs + lane + 32];

    float logits[9];
    #pragma unroll
    for (int kk = 0; kk < 9; kk++) {
        int y = h + (kk / 3 - 1) * dil;
        int xx = x + (kk % 3 - 1) * dil;
        float p = 0.f;
        if (y >= 0 && y < H_ && xx >= 0 && xx < W_) {
            const float* kp = kb + ((b << 12) + (y << 6) + xx) * kstride + kofs;
            p = q0 * kp[lane] + q1 * kp[lane + 32];
        }
        #pragma unroll
        for (int s = 16; s; s >>= 1) p += __shfl_xor_sync(0xffffffffu, p, s);
        logits[kk] = p * 0.125f;
    }

    float mx = logits[0];
    #pragma unroll
    for (int kk = 1; kk < 9; kk++) mx = fmaxf(mx, logits[kk]);
    float e[9], den = 0.f;
    #pragma unroll
    for (int kk = 0; kk < 9; kk++) { e[kk] = __expf(logits[kk] - mx); den += e[kk]; }
    float inv = 1.f / den;

    float o0 = 0.f, o1 = 0.f;
    #pragma unroll
    for (int kk = 0; kk < 9; kk++) {
        int y = h + (kk / 3 - 1) * dil;
        int xx = x + (kk % 3 - 1) * dil;
        if (y >= 0 && y < H_ && xx >= 0 && xx < W_) {
            const float* vp = vb + ((b << 12) + (y << 6) + xx) * kstride + vofs;
            float a = e[kk] * inv;
            o0 += a * vp[lane];
            o1 += a * vp[lane + 32];
        }
    }
    ob[pos * C_ + qofs + lane]      = o0;
    ob[pos * C_ + qofs + lane + 32] = o1;
}

// ---------------------------------------------------------------------------
// Launch
// ---------------------------------------------------------------------------
extern "C" void kernel_launch(void* const* d_in, const int* in_sizes, int n_in,
                              void* d_out, int out_size)
{
    const float* x      = (const float*)d_in[0];
    const float* qkv_w  = (const float*)d_in[1];
    const float* proj_w = (const float*)d_in[2];
    const float* proj_b = (const float*)d_in[3];
    const float* off_w2 = (const float*)d_in[4];
    const float* off_b2 = (const float*)d_in[5];
    const float* def_w2 = (const float*)d_in[6];
    const float* def_b2 = (const float*)d_in[7];
    const float* off_w3 = (const float*)d_in[8];
    const float* off_b3 = (const float*)d_in[9];
    const float* def_w3 = (const float*)d_in[10];
    const float* def_b3 = (const float*)d_in[11];
    float* out = (float*)d_out;

    float *p_qkv, *p_G, *p_dk2, *p_dv2, *p_dk3, *p_dv3, *p_attn, *p_wc;
    cudaGetSymbolAddress((void**)&p_qkv,  g_qkv);
    cudaGetSymbolAddress((void**)&p_G,    g_G);
    cudaGetSymbolAddress((void**)&p_dk2,  g_defk2);
    cudaGetSymbolAddress((void**)&p_dv2,  g_defv2);
    cudaGetSymbolAddress((void**)&p_dk3,  g_defk3);
    cudaGetSymbolAddress((void**)&p_dv3,  g_defv3);
    cudaGetSymbolAddress((void**)&p_attn, g_attn);
    cudaGetSymbolAddress((void**)&p_wc,   g_Wc);

    // 0) combined deform/offset weights
    build_w<<<(2 * GN * HD + 255) / 256, 256>>>(def_w2, off_w2, def_w3, off_w3, p_wc);

    // 1) qkv = x @ qkv_w^T
    mma_nt<<<dim3(QKVC / BN, M_ / BM), 128>>>(x, C_, qkv_w, C_, nullptr, p_qkv, QKVC, C_);

    // 2) all four G projections (k2,v2,k3,v3) incl. fused offsets conv
    mma_g<<<dim3(GN / BN, M_ / BM, 4), 128>>>(p_qkv, p_wc, p_G);

    // 3) deformable gather, both branches
    deform_gather<<<dim3(M_ / 8, 2), 256>>>(p_G, off_b2, def_b2, off_b3, def_b3,
                                            p_dk2, p_dv2, p_dk3, p_dv3);

    // 4) attention, all branches
    attn_all<<<dim3(M_ / 8, 3), 256>>>(p_qkv, p_dk2, p_dv2, p_dk3, p_dv3, p_attn);

    // 5) out = attn @ proj_w^T + proj_b
    mma_nt<<<dim3(C_ / BN, M_ / BM), 128>>>(p_attn, C_, proj_w, C_, proj_b, out, C_, C_);
}

// round 6
// speedup vs baseline: 5.5131x; 1.3945x over previous
#include <cuda_runtime.h>
#include <cuda_fp16.h>
#include <math.h>

#define B_   8
#define H_   64
#define W_   64
#define M_   32768
#define C_   192
#define QKVC 576
#define HD   64
#define GN   768   // G row stride: 576 (Gk/Gv) + 162 (OffG) + pad

// ---------------------------------------------------------------------------
// Scratch (static device globals)
// ---------------------------------------------------------------------------
__device__ float  g_qkv[M_ * QKVC];      // [pos][576] fp32
__device__ __half g_G[4][M_ * GN];       // z = {k2, v2, k3, v3}, fp16
__device__ float  g_defk2[M_ * HD];
__device__ float  g_defv2[M_ * HD];
__device__ float  g_defk3[M_ * HD];
__device__ float  g_defv3[M_ * HD];
__device__ float  g_attn[M_ * C_];       // [pos][branch*64+c]
__device__ float  g_Wc[2][GN * HD];      // combined [def | off] weights per branch

// ---------------------------------------------------------------------------
// fp16 MMA helpers
// ---------------------------------------------------------------------------
__device__ __forceinline__ void mma_f16(float (&d)[4], const unsigned (&a)[4],
                                        const unsigned b0, const unsigned b1) {
    asm volatile(
        "mma.sync.aligned.m16n8k16.row.col.f32.f16.f16.f32 "
        "{%0,%1,%2,%3}, {%4,%5,%6,%7}, {%8,%9}, {%0,%1,%2,%3};\n"
        : "+f"(d[0]), "+f"(d[1]), "+f"(d[2]), "+f"(d[3])
        : "r"(a[0]), "r"(a[1]), "r"(a[2]), "r"(a[3]), "r"(b0), "r"(b1));
}

__device__ __forceinline__ void ldsm4(unsigned (&r)[4], unsigned addr) {
    asm volatile("ldmatrix.sync.aligned.m8n8.x4.shared.b16 {%0,%1,%2,%3}, [%4];"
                 : "=r"(r[0]), "=r"(r[1]), "=r"(r[2]), "=r"(r[3]) : "r"(addr));
}

__device__ __forceinline__ uint2 pack_h4(float4 f) {
    __half2 h01 = __float22half2_rn(make_float2(f.x, f.y));
    __half2 h23 = __float22half2_rn(make_float2(f.z, f.w));
    uint2 v;
    v.x = *reinterpret_cast<unsigned*>(&h01);
    v.y = *reinterpret_cast<unsigned*>(&h23);
    return v;
}

// ---------------------------------------------------------------------------
// fp16 NT GEMM core. Block 128x64, 4 warps (2x2), warp tile 64x32, BK=16,
// double-buffered. Smem rows: 16 halfs of k + pad, PADW=12 words (48B) so
// all 8 ldmatrix rows per 8x8 tile land in distinct bank groups.
// A fragments via ldmatrix.x4 (mats: rows0-7/k0, rows8-15/k0, rows0-7/k8,
// rows8-15/k8 -> exactly MMA A reg order). B (NT, [n][k] rows) needs no
// transpose: mats nj0/k0, nj0/k8, nj1/k0, nj1/k8 -> two MMAs' B regs.
// ---------------------------------------------------------------------------
#define BM 128
#define BN 64
#define PADW 12
#define ABUFW (BM * PADW)       // words per A buffer
#define BBUFW (BN * PADW)

template<bool HOUT>
__device__ __forceinline__ void gemm16(
    const float* __restrict__ A, int lda,
    const float* __restrict__ Wt, int ldb,
    const float* __restrict__ bias, void* __restrict__ Cp, int ldc,
    int m0, int n0, int Kd, unsigned* As, unsigned* Bs)
{
    const int tid  = threadIdx.x;
    const int lane = tid & 31;
    const int warp = tid >> 5;
    const int wm = warp >> 1, wn = warp & 1;
    const int g = lane >> 2, t = lane & 3;
    const int lrow = tid >> 2, lkq = tid & 3;

    // ldmatrix lane addresses (word indices within buffer 0)
    unsigned a_base = (unsigned)__cvta_generic_to_shared(As);
    unsigned b_base = (unsigned)__cvta_generic_to_shared(Bs);
    unsigned aaddr[4], baddr[2];
    {
        int mrow = ((lane >> 3) & 1) * 8 + (lane & 7);
        int ah = (lane >> 4);                       // k-half
        #pragma unroll
        for (int mi = 0; mi < 4; mi++)
            aaddr[mi] = a_base + ((wm * 64 + mi * 16 + mrow) * PADW + ah * 4) * 4u;
        int bh = (lane >> 3) & 1;
        int brow0 = ((lane >> 4) & 1) * 8 + (lane & 7); // (matid>>1)*8 + r
        #pragma unroll
        for (int np = 0; np < 2; np++)
            baddr[np] = b_base + ((wn * 32 + np * 16 + brow0) * PADW + bh * 4) * 4u;
    }

    float acc[4][4][4] = {};
    const int nit = Kd >> 4;
    float4 ra[4], rb[2];

    // prefetch stage 0
    #pragma unroll
    for (int i = 0; i < 4; i++)
        ra[i] = *reinterpret_cast<const float4*>(&A[(size_t)(m0 + lrow + 32 * i) * lda + lkq * 4]);
    #pragma unroll
    for (int i = 0; i < 2; i++)
        rb[i] = *reinterpret_cast<const float4*>(&Wt[(size_t)(n0 + lrow + 32 * i) * ldb + lkq * 4]);
    #pragma unroll
    for (int i = 0; i < 4; i++)
        *reinterpret_cast<uint2*>(&As[(lrow + 32 * i) * PADW + lkq * 2]) = pack_h4(ra[i]);
    #pragma unroll
    for (int i = 0; i < 2; i++)
        *reinterpret_cast<uint2*>(&Bs[(lrow + 32 * i) * PADW + lkq * 2]) = pack_h4(rb[i]);
    __syncthreads();

    for (int it = 0; it < nit; it++) {
        const int buf = it & 1;
        const bool more = (it + 1) < nit;
        const unsigned abytes = buf * (ABUFW * 4);
        const unsigned bbytes = buf * (BBUFW * 4);

        if (more) {
            int k0 = (it + 1) << 4;
            #pragma unroll
            for (int i = 0; i < 4; i++)
                ra[i] = *reinterpret_cast<const float4*>(&A[(size_t)(m0 + lrow + 32 * i) * lda + k0 + lkq * 4]);
            #pragma unroll
            for (int i = 0; i < 2; i++)
                rb[i] = *reinterpret_cast<const float4*>(&Wt[(size_t)(n0 + lrow + 32 * i) * ldb + k0 + lkq * 4]);
        }

        unsigned af[4][4], bf[2][4];
        #pragma unroll
        for (int mi = 0; mi < 4; mi++) ldsm4(af[mi], aaddr[mi] + abytes);
        #pragma unroll
        for (int np = 0; np < 2; np++) ldsm4(bf[np], baddr[np] + bbytes);

        #pragma unroll
        for (int mi = 0; mi < 4; mi++)
            #pragma unroll
            for (int nj = 0; nj < 4; nj++)
                mma_f16(acc[mi][nj], af[mi], bf[nj >> 1][(nj & 1) * 2], bf[nj >> 1][(nj & 1) * 2 + 1]);

        if (more) {
            const int nb = (it + 1) & 1;
            #pragma unroll
            for (int i = 0; i < 4; i++)
                *reinterpret_cast<uint2*>(&As[nb * ABUFW + (lrow + 32 * i) * PADW + lkq * 2]) = pack_h4(ra[i]);
            #pragma unroll
            for (int i = 0; i < 2; i++)
                *reinterpret_cast<uint2*>(&Bs[nb * BBUFW + (lrow + 32 * i) * PADW + lkq * 2]) = pack_h4(rb[i]);
            __syncthreads();
        }
    }

    // epilogue (m16n8 C layout: c0,c1 = (g, 2t..2t+1), c2,c3 = (g+8, ...))
    #pragma unroll
    for (int mi = 0; mi < 4; mi++) {
        int r = m0 + wm * 64 + mi * 16 + g;
        #pragma unroll
        for (int nj = 0; nj < 4; nj++) {
            int c = n0 + wn * 32 + nj * 8 + 2 * t;
            float b0 = bias ? bias[c] : 0.f;
            float b1 = bias ? bias[c + 1] : 0.f;
            float v0 = acc[mi][nj][0] + b0, v1 = acc[mi][nj][1] + b1;
            float v2 = acc[mi][nj][2] + b0, v3 = acc[mi][nj][3] + b1;
            if (HOUT) {
                __half* Ch = (__half*)Cp;
                *reinterpret_cast<__half2*>(&Ch[(size_t)r * ldc + c]) =
                    __float22half2_rn(make_float2(v0, v1));
                *reinterpret_cast<__half2*>(&Ch[(size_t)(r + 8) * ldc + c]) =
                    __float22half2_rn(make_float2(v2, v3));
            } else {
                float* Cf = (float*)Cp;
                *reinterpret_cast<float2*>(&Cf[(size_t)r * ldc + c]) = make_float2(v0, v1);
                *reinterpret_cast<float2*>(&Cf[(size_t)(r + 8) * ldc + c]) = make_float2(v2, v3);
            }
        }
    }
}

__global__ __launch_bounds__(128) void mma_nt(
    const float* __restrict__ A, int lda,
    const float* __restrict__ Wt, int ldb,
    const float* __restrict__ bias, float* __restrict__ C,
    int ldc, int Kd)
{
    __shared__ __align__(16) unsigned As[2 * ABUFW];
    __shared__ __align__(16) unsigned Bs[2 * BBUFW];
    gemm16<false>(A, lda, Wt, ldb, bias, C, ldc,
                  blockIdx.y * BM, blockIdx.x * BN, Kd, As, Bs);
}

// Merged G GEMMs: z = {k2, v2, k3, v3}. A = qkv slice [M x 64], lda = 576.
// W = g_Wc[branch] [768 x 64]. Out = g_G[z] [M x 768] fp16. K = 64.
// v slices (z odd) skip the OffG columns (n0 >= 576).
__global__ __launch_bounds__(128) void mma_g(
    const float* __restrict__ qkv, const float* __restrict__ Wc,
    __half* __restrict__ G)
{
    const int z = blockIdx.z;
    const int n0 = blockIdx.x * BN;
    if ((z & 1) && n0 >= QKVC) return;
    __shared__ __align__(16) unsigned As[2 * ABUFW];
    __shared__ __align__(16) unsigned Bs[2 * BBUFW];
    const int ofsA = 256 + (z >> 1) * 64 + (z & 1) * 192;
    gemm16<true>(qkv + ofsA, QKVC, Wc + (size_t)(z >> 1) * GN * HD, HD, nullptr,
                 G + (size_t)z * M_ * GN, GN, blockIdx.y * BM, n0, HD, As, Bs);
}

// ---------------------------------------------------------------------------
// Build combined weights: rows 0..575: W2[kk*64+o][c] = def_w[o][c][kk]
//                         rows 576..737: Woff[kk*18+o][c] = off_w[o][c][kk]
//                         rows 738..767: zero
// ---------------------------------------------------------------------------
__global__ void build_w(const float* __restrict__ dw2, const float* __restrict__ ow2,
                        const float* __restrict__ dw3, const float* __restrict__ ow3,
                        float* __restrict__ Wc)
{
    int i = blockIdx.x * blockDim.x + threadIdx.x;
    if (i >= 2 * GN * HD) return;
    int br = i / (GN * HD);
    int r  = (i / HD) % GN;
    int c  = i % HD;
    const float* dw = br ? dw3 : dw2;
    const float* ow = br ? ow3 : ow2;
    float v = 0.f;
    if (r < QKVC) {
        int kk = r >> 6, o = r & 63;
        v = dw[o * 576 + c * 9 + kk];
    } else if (r < QKVC + 162) {
        int rr = r - QKVC, kk = rr / 18, o = rr % 18;
        v = ow[o * 576 + c * 9 + kk];
    }
    Wc[i] = v;
}

// ---------------------------------------------------------------------------
// Deformable gather, both branches (blockIdx.y). One warp per position.
// Phase 1: lanes 0..17 accumulate offsets via integer 9-tap gather of OffG.
// Phase 2: lanes 0..8 compute per-tap bilinear corner indices + masked
//          weights; broadcast via shfl; all lanes accumulate k|v channels.
// G is fp16.
// ---------------------------------------------------------------------------
__global__ __launch_bounds__(256) void deform_gather(
    const __half* __restrict__ G,
    const float* __restrict__ ob2, const float* __restrict__ db2,
    const float* __restrict__ ob3, const float* __restrict__ db3,
    float* __restrict__ dk2, float* __restrict__ dv2,
    float* __restrict__ dk3, float* __restrict__ dv3)
{
    const int br  = blockIdx.y;
    const int dil = br + 2;
    const __half* __restrict__ Gk = G + (size_t)(2 * br) * M_ * GN;
    const __half* __restrict__ Gv = G + (size_t)(2 * br + 1) * M_ * GN;
    const float* offb = br ? ob3 : ob2;
    const float* defb = br ? db3 : db2;
    float* dk = br ? dk3 : dk2;
    float* dv = br ? dv3 : dv2;

    const int warp = threadIdx.x >> 5, lane = threadIdx.x & 31;
    const int pos = (blockIdx.x << 3) + warp;
    const int b = pos >> 12, hw = pos & 4095, h = hw >> 6, x = hw & 63;
    const int rbase = b << 12;

    // Phase 1: offsets (18 channels on lanes 0..17)
    float offa = (lane < 18) ? offb[lane] : 0.f;
    #pragma unroll
    for (int kq = 0; kq < 9; kq++) {
        int y  = h + (kq / 3 - 1) * dil;
        int xx = x + (kq % 3 - 1) * dil;
        if (lane < 18 && y >= 0 && y < H_ && xx >= 0 && xx < W_)
            offa += __half2float(Gk[(size_t)(rbase + (y << 6) + xx) * GN + QKVC + kq * 18 + lane]);
    }

    // Phase 2: per-tap bilinear setup (lanes 0..8 meaningful)
    int kk = lane;
    float offy = __shfl_sync(0xffffffffu, offa, (2 * lane) & 31);
    float offx = __shfl_sync(0xffffffffu, offa, (2 * lane + 1) & 31);
    float py = (float)h + (float)((kk / 3) * dil - dil) + offy;
    float px = (float)x + (float)((kk % 3) * dil - dil) + offx;
    float y0f = floorf(py), x0f = floorf(px);
    float wy = py - y0f, wx = px - x0f;
    int y0 = (int)y0f, x0 = (int)x0f, y1 = y0 + 1, x1 = x0 + 1;
    float fy0 = (float)(y0 >= 0 && y0 < H_);
    float fy1 = (float)(y1 >= 0 && y1 < H_);
    float fx0 = (float)(x0 >= 0 && x0 < W_);
    float fx1 = (float)(x1 >= 0 && x1 < W_);
    float w00 = (1.f - wy) * (1.f - wx) * fy0 * fx0;
    float w01 = (1.f - wy) * wx        * fy0 * fx1;
    float w10 = wy * (1.f - wx)        * fy1 * fx0;
    float w11 = wy * wx                * fy1 * fx1;
    int y0c = min(max(y0, 0), H_ - 1), y1c = min(max(y1, 0), H_ - 1);
    int x0c = min(max(x0, 0), W_ - 1), x1c = min(max(x1, 0), W_ - 1);
    int tapofs = kk * 64;
    int i00 = (rbase + (y0c << 6) + x0c) * GN + tapofs;
    int i01 = (rbase + (y0c << 6) + x1c) * GN + tapofs;
    int i10 = (rbase + (y1c << 6) + x0c) * GN + tapofs;
    int i11 = (rbase + (y1c << 6) + x1c) * GN + tapofs;

    const int arr = lane >> 4;            // 0 = k, 1 = v
    const int c4 = (lane & 15) * 4;
    const __half* __restrict__ Gs = arr ? Gv : Gk;

    float4 acc = *reinterpret_cast<const float4*>(&defb[c4]);

    #pragma unroll
    for (int tp = 0; tp < 9; tp++) {
        float a00 = __shfl_sync(0xffffffffu, w00, tp);
        float a01 = __shfl_sync(0xffffffffu, w01, tp);
        float a10 = __shfl_sync(0xffffffffu, w10, tp);
        float a11 = __shfl_sync(0xffffffffu, w11, tp);
        int   j00 = __shfl_sync(0xffffffffu, i00, tp);
        int   j01 = __shfl_sync(0xffffffffu, i01, tp);
        int   j10 = __shfl_sync(0xffffffffu, i10, tp);
        int   j11 = __shfl_sync(0xffffffffu, i11, tp);
        __half2 p0, p1;
        uint2 raw;
        raw = *reinterpret_cast<const uint2*>(&Gs[j00 + c4]);
        p0 = *reinterpret_cast<__half2*>(&raw.x); p1 = *reinterpret_cast<__half2*>(&raw.y);
        { float2 lo = __half22float2(p0), hi = __half22float2(p1);
          acc.x += a00 * lo.x; acc.y += a00 * lo.y; acc.z += a00 * hi.x; acc.w += a00 * hi.y; }
        raw = *reinterpret_cast<const uint2*>(&Gs[j01 + c4]);
        p0 = *reinterpret_cast<__half2*>(&raw.x); p1 = *reinterpret_cast<__half2*>(&raw.y);
        { float2 lo = __half22float2(p0), hi = __half22float2(p1);
          acc.x += a01 * lo.x; acc.y += a01 * lo.y; acc.z += a01 * hi.x; acc.w += a01 * hi.y; }
        raw = *reinterpret_cast<const uint2*>(&Gs[j10 + c4]);
        p0 = *reinterpret_cast<__half2*>(&raw.x); p1 = *reinterpret_cast<__half2*>(&raw.y);
        { float2 lo = __half22float2(p0), hi = __half22float2(p1);
          acc.x += a10 * lo.x; acc.y += a10 * lo.y; acc.z += a10 * hi.x; acc.w += a10 * hi.y; }
        raw = *reinterpret_cast<const uint2*>(&Gs[j11 + c4]);
        p0 = *reinterpret_cast<__half2*>(&raw.x); p1 = *reinterpret_cast<__half2*>(&raw.y);
        { float2 lo = __half22float2(p0), hi = __half22float2(p1);
          acc.x += a11 * lo.x; acc.y += a11 * lo.y; acc.z += a11 * hi.x; acc.w += a11 * hi.y; }
    }

    float* __restrict__ dst = arr ? dv : dk;
    *reinterpret_cast<float4*>(&dst[pos * HD + c4]) = acc;
}

// ---------------------------------------------------------------------------
// 9-tap local attention, all 3 branches (blockIdx.y). Warp per position.
// ---------------------------------------------------------------------------
__global__ __launch_bounds__(256) void attn_all(
    const float* __restrict__ qkv,
    const float* __restrict__ dk2, const float* __restrict__ dv2,
    const float* __restrict__ dk3, const float* __restrict__ dv3,
    float* __restrict__ ob)
{
    const int br = blockIdx.y;
    const int warp = threadIdx.x >> 5, lane = threadIdx.x & 31;
    const int pos = (blockIdx.x << 3) + warp;
    const int b = pos >> 12, hw = pos & 4095, h = hw >> 6, x = hw & 63;

    const float* kb; const float* vb; int kstride, kofs, vofs, dil;
    if (br == 0)      { kb = qkv; vb = qkv; kstride = QKVC; kofs = 192; vofs = 384; dil = 1; }
    else if (br == 1) { kb = dk2; vb = dv2; kstride = HD;   kofs = 0;   vofs = 0;   dil = 2; }
    else              { kb = dk3; vb = dv3; kstride = HD;   kofs = 0;   vofs = 0;   dil = 3; }

    const int qofs = br * 64;
    float q0 = qkv[pos * QKVC + qofs + lane];
    float q1 = qkv[pos * QKVC + qofs + lane + 32];

    float logits[9];
    #pragma unroll
    for (int kk = 0; kk < 9; kk++) {
        int y = h + (kk / 3 - 1) * dil;
        int xx = x + (kk % 3 - 1) * dil;
        float p = 0.f;
        if (y >= 0 && y < H_ && xx >= 0 && xx < W_) {
            const float* kp = kb + ((b << 12) + (y << 6) + xx) * kstride + kofs;
            p = q0 * kp[lane] + q1 * kp[lane + 32];
        }
        #pragma unroll
        for (int s = 16; s; s >>= 1) p += __shfl_xor_sync(0xffffffffu, p, s);
        logits[kk] = p * 0.125f;
    }

    float mx = logits[0];
    #pragma unroll
    for (int kk = 1; kk < 9; kk++) mx = fmaxf(mx, logits[kk]);
    float e[9], den = 0.f;
    #pragma unroll
    for (int kk = 0; kk < 9; kk++) { e[kk] = __expf(logits[kk] - mx); den += e[kk]; }
    float inv = 1.f / den;

    float o0 = 0.f, o1 = 0.f;
    #pragma unroll
    for (int kk = 0; kk < 9; kk++) {
        int y = h + (kk / 3 - 1) * dil;
        int xx = x + (kk % 3 - 1) * dil;
        if (y >= 0 && y < H_ && xx >= 0 && xx < W_) {
            const float* vp = vb + ((b << 12) + (y << 6) + xx) * kstride + vofs;
            float a = e[kk] * inv;
            o0 += a * vp[lane];
            o1 += a * vp[lane + 32];
        }
    }
    ob[pos * C_ + qofs + lane]      = o0;
    ob[pos * C_ + qofs + lane + 32] = o1;
}

// ---------------------------------------------------------------------------
// Launch
// ---------------------------------------------------------------------------
extern "C" void kernel_launch(void* const* d_in, const int* in_sizes, int n_in,
                              void* d_out, int out_size)
{
    const float* x      = (const float*)d_in[0];
    const float* qkv_w  = (const float*)d_in[1];
    const float* proj_w = (const float*)d_in[2];
    const float* proj_b = (const float*)d_in[3];
    const float* off_w2 = (const float*)d_in[4];
    const float* off_b2 = (const float*)d_in[5];
    const float* def_w2 = (const float*)d_in[6];
    const float* def_b2 = (const float*)d_in[7];
    const float* off_w3 = (const float*)d_in[8];
    const float* off_b3 = (const float*)d_in[9];
    const float* def_w3 = (const float*)d_in[10];
    const float* def_b3 = (const float*)d_in[11];
    float* out = (float*)d_out;

    float *p_qkv, *p_dk2, *p_dv2, *p_dk3, *p_dv3, *p_attn, *p_wc;
    __half* p_G;
    cudaGetSymbolAddress((void**)&p_qkv,  g_qkv);
    cudaGetSymbolAddress((void**)&p_G,    g_G);
    cudaGetSymbolAddress((void**)&p_dk2,  g_defk2);
    cudaGetSymbolAddress((void**)&p_dv2,  g_defv2);
    cudaGetSymbolAddress((void**)&p_dk3,  g_defk3);
    cudaGetSymbolAddress((void**)&p_dv3,  g_defv3);
    cudaGetSymbolAddress((void**)&p_attn, g_attn);
    cudaGetSymbolAddress((void**)&p_wc,   g_Wc);

    // 0) combined deform/offset weights
    build_w<<<(2 * GN * HD + 255) / 256, 256>>>(def_w2, off_w2, def_w3, off_w3, p_wc);

    // 1) qkv = x @ qkv_w^T
    mma_nt<<<dim3(QKVC / BN, M_ / BM), 128>>>(x, C_, qkv_w, C_, nullptr, p_qkv, QKVC, C_);

    // 2) all four G projections (k2,v2,k3,v3) incl. fused offsets conv
    mma_g<<<dim3(GN / BN, M_ / BM, 4), 128>>>(p_qkv, p_wc, p_G);

    // 3) deformable gather, both branches
    deform_gather<<<dim3(M_ / 8, 2), 256>>>(p_G, off_b2, def_b2, off_b3, def_b3,
                                            p_dk2, p_dv2, p_dk3, p_dv3);

    // 4) attention, all branches
    attn_all<<<dim3(M_ / 8, 3), 256>>>(p_qkv, p_dk2, p_dv2, p_dk3, p_dv3, p_attn);

    // 5) out = attn @ proj_w^T + proj_b
    mma_nt<<<dim3(C_ / BN, M_ / BM), 128>>>(p_attn, C_, proj_w, C_, proj_b, out, C_, C_);
}

// round 7
// speedup vs baseline: 5.7451x; 1.0421x over previous
#include <cuda_runtime.h>
#include <cuda_fp16.h>
#include <math.h>

#define B_   8
#define H_   64
#define W_   64
#define M_   32768
#define C_   192
#define QKVC 576
#define HD   64
#define GN   768   // G row stride: 576 (Gk/Gv) + 162 (OffG) + pad

// ---------------------------------------------------------------------------
// Scratch (static device globals) — fp16 end-to-end intermediates
// ---------------------------------------------------------------------------
__device__ __half g_qkv[M_ * QKVC];      // [pos][576]
__device__ __half g_G[4][M_ * GN];       // z = {k2, v2, k3, v3}
__device__ __half g_dk2[M_ * HD];
__device__ __half g_dv2[M_ * HD];
__device__ __half g_dk3[M_ * HD];
__device__ __half g_dv3[M_ * HD];
__device__ __half g_attn[M_ * C_];       // [pos][branch*64+c]
__device__ __half g_Wc[2][GN * HD];      // combined [def | off] weights per branch

// ---------------------------------------------------------------------------
// fp16 MMA helpers
// ---------------------------------------------------------------------------
__device__ __forceinline__ void mma_f16(float (&d)[4], const unsigned (&a)[4],
                                        const unsigned b0, const unsigned b1) {
    asm volatile(
        "mma.sync.aligned.m16n8k16.row.col.f32.f16.f16.f32 "
        "{%0,%1,%2,%3}, {%4,%5,%6,%7}, {%8,%9}, {%0,%1,%2,%3};\n"
        : "+f"(d[0]), "+f"(d[1]), "+f"(d[2]), "+f"(d[3])
        : "r"(a[0]), "r"(a[1]), "r"(a[2]), "r"(a[3]), "r"(b0), "r"(b1));
}

__device__ __forceinline__ void ldsm4(unsigned (&r)[4], unsigned addr) {
    asm volatile("ldmatrix.sync.aligned.m8n8.x4.shared.b16 {%0,%1,%2,%3}, [%4];"
                 : "=r"(r[0]), "=r"(r[1]), "=r"(r[2]), "=r"(r[3]) : "r"(addr));
}

__device__ __forceinline__ uint2 pack_h4(float4 f) {
    __half2 h01 = __float22half2_rn(make_float2(f.x, f.y));
    __half2 h23 = __float22half2_rn(make_float2(f.z, f.w));
    uint2 v;
    v.x = *reinterpret_cast<unsigned*>(&h01);
    v.y = *reinterpret_cast<unsigned*>(&h23);
    return v;
}

// Typed 4-k-element loader (float: float4 + cvt; half: direct uint2)
template<typename T> struct RawVec;
template<> struct RawVec<float> {
    float4 v;
    __device__ __forceinline__ void load(const float* p) { v = *reinterpret_cast<const float4*>(p); }
    __device__ __forceinline__ uint2 pack() const { return pack_h4(v); }
};
template<> struct RawVec<__half> {
    uint2 v;
    __device__ __forceinline__ void load(const __half* p) { v = *reinterpret_cast<const uint2*>(p); }
    __device__ __forceinline__ uint2 pack() const { return v; }
};

// ---------------------------------------------------------------------------
// fp16 NT GEMM core. Block 128x64, 4 warps (2x2), warp tile 64x32, BK=16,
// double-buffered, ldmatrix fragments. PADW=12 words keeps ldmatrix rows on
// distinct bank groups.
// ---------------------------------------------------------------------------
#define BM 128
#define BN 64
#define PADW 12
#define ABUFW (BM * PADW)
#define BBUFW (BN * PADW)

template<typename TA, typename TB, bool HOUT>
__device__ __forceinline__ void gemm16(
    const TA* __restrict__ A, int lda,
    const TB* __restrict__ Wt, int ldb,
    const float* __restrict__ bias, void* __restrict__ Cp, int ldc,
    int m0, int n0, int Kd, unsigned* As, unsigned* Bs)
{
    const int tid  = threadIdx.x;
    const int lane = tid & 31;
    const int warp = tid >> 5;
    const int wm = warp >> 1, wn = warp & 1;
    const int g = lane >> 2, t = lane & 3;
    const int lrow = tid >> 2, lkq = tid & 3;

    unsigned a_base = (unsigned)__cvta_generic_to_shared(As);
    unsigned b_base = (unsigned)__cvta_generic_to_shared(Bs);
    unsigned aaddr[4], baddr[2];
    {
        int mrow = ((lane >> 3) & 1) * 8 + (lane & 7);
        int ah = (lane >> 4);
        #pragma unroll
        for (int mi = 0; mi < 4; mi++)
            aaddr[mi] = a_base + ((wm * 64 + mi * 16 + mrow) * PADW + ah * 4) * 4u;
        int bh = (lane >> 3) & 1;
        int brow0 = ((lane >> 4) & 1) * 8 + (lane & 7);
        #pragma unroll
        for (int np = 0; np < 2; np++)
            baddr[np] = b_base + ((wn * 32 + np * 16 + brow0) * PADW + bh * 4) * 4u;
    }

    float acc[4][4][4] = {};
    const int nit = Kd >> 4;
    RawVec<TA> ra[4];
    RawVec<TB> rb[2];

    #pragma unroll
    for (int i = 0; i < 4; i++)
        ra[i].load(&A[(size_t)(m0 + lrow + 32 * i) * lda + lkq * 4]);
    #pragma unroll
    for (int i = 0; i < 2; i++)
        rb[i].load(&Wt[(size_t)(n0 + lrow + 32 * i) * ldb + lkq * 4]);
    #pragma unroll
    for (int i = 0; i < 4; i++)
        *reinterpret_cast<uint2*>(&As[(lrow + 32 * i) * PADW + lkq * 2]) = ra[i].pack();
    #pragma unroll
    for (int i = 0; i < 2; i++)
        *reinterpret_cast<uint2*>(&Bs[(lrow + 32 * i) * PADW + lkq * 2]) = rb[i].pack();
    __syncthreads();

    for (int it = 0; it < nit; it++) {
        const int buf = it & 1;
        const bool more = (it + 1) < nit;
        const unsigned abytes = buf * (ABUFW * 4);
        const unsigned bbytes = buf * (BBUFW * 4);

        if (more) {
            int k0 = (it + 1) << 4;
            #pragma unroll
            for (int i = 0; i < 4; i++)
                ra[i].load(&A[(size_t)(m0 + lrow + 32 * i) * lda + k0 + lkq * 4]);
            #pragma unroll
            for (int i = 0; i < 2; i++)
                rb[i].load(&Wt[(size_t)(n0 + lrow + 32 * i) * ldb + k0 + lkq * 4]);
        }

        unsigned af[4][4], bf[2][4];
        #pragma unroll
        for (int mi = 0; mi < 4; mi++) ldsm4(af[mi], aaddr[mi] + abytes);
        #pragma unroll
        for (int np = 0; np < 2; np++) ldsm4(bf[np], baddr[np] + bbytes);

        #pragma unroll
        for (int mi = 0; mi < 4; mi++)
            #pragma unroll
            for (int nj = 0; nj < 4; nj++)
                mma_f16(acc[mi][nj], af[mi], bf[nj >> 1][(nj & 1) * 2], bf[nj >> 1][(nj & 1) * 2 + 1]);

        if (more) {
            const int nb = (it + 1) & 1;
            #pragma unroll
            for (int i = 0; i < 4; i++)
                *reinterpret_cast<uint2*>(&As[nb * ABUFW + (lrow + 32 * i) * PADW + lkq * 2]) = ra[i].pack();
            #pragma unroll
            for (int i = 0; i < 2; i++)
                *reinterpret_cast<uint2*>(&Bs[nb * BBUFW + (lrow + 32 * i) * PADW + lkq * 2]) = rb[i].pack();
            __syncthreads();
        }
    }

    #pragma unroll
    for (int mi = 0; mi < 4; mi++) {
        int r = m0 + wm * 64 + mi * 16 + g;
        #pragma unroll
        for (int nj = 0; nj < 4; nj++) {
            int c = n0 + wn * 32 + nj * 8 + 2 * t;
            float b0 = bias ? bias[c] : 0.f;
            float b1 = bias ? bias[c + 1] : 0.f;
            float v0 = acc[mi][nj][0] + b0, v1 = acc[mi][nj][1] + b1;
            float v2 = acc[mi][nj][2] + b0, v3 = acc[mi][nj][3] + b1;
            if (HOUT) {
                __half* Ch = (__half*)Cp;
                *reinterpret_cast<__half2*>(&Ch[(size_t)r * ldc + c]) =
                    __float22half2_rn(make_float2(v0, v1));
                *reinterpret_cast<__half2*>(&Ch[(size_t)(r + 8) * ldc + c]) =
                    __float22half2_rn(make_float2(v2, v3));
            } else {
                float* Cf = (float*)Cp;
                *reinterpret_cast<float2*>(&Cf[(size_t)r * ldc + c]) = make_float2(v0, v1);
                *reinterpret_cast<float2*>(&Cf[(size_t)(r + 8) * ldc + c]) = make_float2(v2, v3);
            }
        }
    }
}

// qkv = x @ qkv_w^T  (fp32 in, fp16 out)
__global__ __launch_bounds__(128) void mma_qkv(
    const float* __restrict__ x, const float* __restrict__ w,
    __half* __restrict__ C)
{
    __shared__ __align__(16) unsigned As[2 * ABUFW];
    __shared__ __align__(16) unsigned Bs[2 * BBUFW];
    gemm16<float, float, true>(x, C_, w, C_, nullptr, C, QKVC,
                               blockIdx.y * BM, blockIdx.x * BN, C_, As, Bs);
}

// Merged G GEMMs: z = {k2, v2, k3, v3}; fp16 A (qkv slice), fp16 W, fp16 out.
__global__ __launch_bounds__(128) void mma_g(
    const __half* __restrict__ qkv, const __half* __restrict__ Wc,
    __half* __restrict__ G)
{
    const int z = blockIdx.z;
    const int n0 = blockIdx.x * BN;
    if ((z & 1) && n0 >= QKVC) return;
    __shared__ __align__(16) unsigned As[2 * ABUFW];
    __shared__ __align__(16) unsigned Bs[2 * BBUFW];
    const int ofsA = 256 + (z >> 1) * 64 + (z & 1) * 192;
    gemm16<__half, __half, true>(qkv + ofsA, QKVC, Wc + (size_t)(z >> 1) * GN * HD, HD,
                                 nullptr, G + (size_t)z * M_ * GN, GN,
                                 blockIdx.y * BM, n0, HD, As, Bs);
}

// out = attn @ proj_w^T + proj_b  (fp16 A, fp32 W, fp32 out)
__global__ __launch_bounds__(128) void mma_proj(
    const __half* __restrict__ A, const float* __restrict__ w,
    const float* __restrict__ bias, float* __restrict__ out)
{
    __shared__ __align__(16) unsigned As[2 * ABUFW];
    __shared__ __align__(16) unsigned Bs[2 * BBUFW];
    gemm16<__half, float, false>(A, C_, w, C_, bias, out, C_,
                                 blockIdx.y * BM, blockIdx.x * BN, C_, As, Bs);
}

// ---------------------------------------------------------------------------
// Build combined weights (fp16): rows 0..575: def_w[o][c][kk] -> [kk*64+o][c]
//                                rows 576..737: off_w -> [576 + kk*18+o][c]
// ---------------------------------------------------------------------------
__global__ void build_w(const float* __restrict__ dw2, const float* __restrict__ ow2,
                        const float* __restrict__ dw3, const float* __restrict__ ow3,
                        __half* __restrict__ Wc)
{
    int i = blockIdx.x * blockDim.x + threadIdx.x;
    if (i >= 2 * GN * HD) return;
    int br = i / (GN * HD);
    int r  = (i / HD) % GN;
    int c  = i % HD;
    const float* dw = br ? dw3 : dw2;
    const float* ow = br ? ow3 : ow2;
    float v = 0.f;
    if (r < QKVC) {
        int kk = r >> 6, o = r & 63;
        v = dw[o * 576 + c * 9 + kk];
    } else if (r < QKVC + 162) {
        int rr = r - QKVC, kk = rr / 18, o = rr % 18;
        v = ow[o * 576 + c * 9 + kk];
    }
    Wc[i] = __float2half(v);
}

// ---------------------------------------------------------------------------
// Deformable gather, both branches (blockIdx.y). One warp per position.
// Phase 1: lanes 0..17 accumulate offsets from OffG columns of Gk.
// Phase 2: lanes 0..8 compute per-tap bilinear corners; shfl-broadcast;
//          all lanes accumulate k|v channels (fp16 in, fp16 out).
// ---------------------------------------------------------------------------
__global__ __launch_bounds__(256) void deform_gather(
    const __half* __restrict__ G,
    const float* __restrict__ ob2, const float* __restrict__ db2,
    const float* __restrict__ ob3, const float* __restrict__ db3,
    __half* __restrict__ dk2, __half* __restrict__ dv2,
    __half* __restrict__ dk3, __half* __restrict__ dv3)
{
    const int br  = blockIdx.y;
    const int dil = br + 2;
    const __half* __restrict__ Gk = G + (size_t)(2 * br) * M_ * GN;
    const __half* __restrict__ Gv = G + (size_t)(2 * br + 1) * M_ * GN;
    const float* offb = br ? ob3 : ob2;
    const float* defb = br ? db3 : db2;
    __half* dk = br ? dk3 : dk2;
    __half* dv = br ? dv3 : dv2;

    const int warp = threadIdx.x >> 5, lane = threadIdx.x & 31;
    const int pos = (blockIdx.x << 3) + warp;
    const int b = pos >> 12, hw = pos & 4095, h = hw >> 6, x = hw & 63;
    const int rbase = b << 12;

    // Phase 1: offsets (18 channels on lanes 0..17)
    float offa = (lane < 18) ? offb[lane] : 0.f;
    #pragma unroll
    for (int kq = 0; kq < 9; kq++) {
        int y  = h + (kq / 3 - 1) * dil;
        int xx = x + (kq % 3 - 1) * dil;
        if (lane < 18 && y >= 0 && y < H_ && xx >= 0 && xx < W_)
            offa += __half2float(Gk[(size_t)(rbase + (y << 6) + xx) * GN + QKVC + kq * 18 + lane]);
    }

    // Phase 2: per-tap bilinear setup (lanes 0..8 meaningful)
    int kk = lane;
    float offy = __shfl_sync(0xffffffffu, offa, (2 * lane) & 31);
    float offx = __shfl_sync(0xffffffffu, offa, (2 * lane + 1) & 31);
    float py = (float)h + (float)((kk / 3) * dil - dil) + offy;
    float px = (float)x + (float)((kk % 3) * dil - dil) + offx;
    float y0f = floorf(py), x0f = floorf(px);
    float wy = py - y0f, wx = px - x0f;
    int y0 = (int)y0f, x0 = (int)x0f, y1 = y0 + 1, x1 = x0 + 1;
    float fy0 = (float)(y0 >= 0 && y0 < H_);
    float fy1 = (float)(y1 >= 0 && y1 < H_);
    float fx0 = (float)(x0 >= 0 && x0 < W_);
    float fx1 = (float)(x1 >= 0 && x1 < W_);
    float w00 = (1.f - wy) * (1.f - wx) * fy0 * fx0;
    float w01 = (1.f - wy) * wx        * fy0 * fx1;
    float w10 = wy * (1.f - wx)        * fy1 * fx0;
    float w11 = wy * wx                * fy1 * fx1;
    int y0c = min(max(y0, 0), H_ - 1), y1c = min(max(y1, 0), H_ - 1);
    int x0c = min(max(x0, 0), W_ - 1), x1c = min(max(x1, 0), W_ - 1);
    int tapofs = kk * 64;
    int i00 = (rbase + (y0c << 6) + x0c) * GN + tapofs;
    int i01 = (rbase + (y0c << 6) + x1c) * GN + tapofs;
    int i10 = (rbase + (y1c << 6) + x0c) * GN + tapofs;
    int i11 = (rbase + (y1c << 6) + x1c) * GN + tapofs;

    const int arr = lane >> 4;            // 0 = k, 1 = v
    const int c4 = (lane & 15) * 4;
    const __half* __restrict__ Gs = arr ? Gv : Gk;

    float4 acc = *reinterpret_cast<const float4*>(&defb[c4]);

    #pragma unroll
    for (int tp = 0; tp < 9; tp++) {
        float a00 = __shfl_sync(0xffffffffu, w00, tp);
        float a01 = __shfl_sync(0xffffffffu, w01, tp);
        float a10 = __shfl_sync(0xffffffffu, w10, tp);
        float a11 = __shfl_sync(0xffffffffu, w11, tp);
        int   j00 = __shfl_sync(0xffffffffu, i00, tp);
        int   j01 = __shfl_sync(0xffffffffu, i01, tp);
        int   j10 = __shfl_sync(0xffffffffu, i10, tp);
        int   j11 = __shfl_sync(0xffffffffu, i11, tp);
        uint2 raw;
        __half2 p0, p1;
        raw = *reinterpret_cast<const uint2*>(&Gs[j00 + c4]);
        p0 = *reinterpret_cast<__half2*>(&raw.x); p1 = *reinterpret_cast<__half2*>(&raw.y);
        { float2 lo = __half22float2(p0), hi = __half22float2(p1);
          acc.x += a00 * lo.x; acc.y += a00 * lo.y; acc.z += a00 * hi.x; acc.w += a00 * hi.y; }
        raw = *reinterpret_cast<const uint2*>(&Gs[j01 + c4]);
        p0 = *reinterpret_cast<__half2*>(&raw.x); p1 = *reinterpret_cast<__half2*>(&raw.y);
        { float2 lo = __half22float2(p0), hi = __half22float2(p1);
          acc.x += a01 * lo.x; acc.y += a01 * lo.y; acc.z += a01 * hi.x; acc.w += a01 * hi.y; }
        raw = *reinterpret_cast<const uint2*>(&Gs[j10 + c4]);
        p0 = *reinterpret_cast<__half2*>(&raw.x); p1 = *reinterpret_cast<__half2*>(&raw.y);
        { float2 lo = __half22float2(p0), hi = __half22float2(p1);
          acc.x += a10 * lo.x; acc.y += a10 * lo.y; acc.z += a10 * hi.x; acc.w += a10 * hi.y; }
        raw = *reinterpret_cast<const uint2*>(&Gs[j11 + c4]);
        p0 = *reinterpret_cast<__half2*>(&raw.x); p1 = *reinterpret_cast<__half2*>(&raw.y);
        { float2 lo = __half22float2(p0), hi = __half22float2(p1);
          acc.x += a11 * lo.x; acc.y += a11 * lo.y; acc.z += a11 * hi.x; acc.w += a11 * hi.y; }
    }

    uint2 st;
    __half2 s01 = __float22half2_rn(make_float2(acc.x, acc.y));
    __half2 s23 = __float22half2_rn(make_float2(acc.z, acc.w));
    st.x = *reinterpret_cast<unsigned*>(&s01);
    st.y = *reinterpret_cast<unsigned*>(&s23);
    __half* __restrict__ dst = arr ? dv : dk;
    *reinterpret_cast<uint2*>(&dst[pos * HD + c4]) = st;
}

// ---------------------------------------------------------------------------
// 9-tap local attention, all 3 branches (blockIdx.y). Warp per position.
// Lane holds channels (2*lane, 2*lane+1) — every tap load/store is one
// coalesced 128B __half2 warp transaction.
// ---------------------------------------------------------------------------
__global__ __launch_bounds__(256) void attn_all(
    const __half* __restrict__ qkv,
    const __half* __restrict__ dk2, const __half* __restrict__ dv2,
    const __half* __restrict__ dk3, const __half* __restrict__ dv3,
    __half* __restrict__ ob)
{
    const int br = blockIdx.y;
    const int warp = threadIdx.x >> 5, lane = threadIdx.x & 31;
    const int pos = (blockIdx.x << 3) + warp;
    const int b = pos >> 12, hw = pos & 4095, h = hw >> 6, x = hw & 63;

    const __half* kb; const __half* vb; int kstride, kofs, vofs, dil;
    if (br == 0)      { kb = qkv; vb = qkv; kstride = QKVC; kofs = 192; vofs = 384; dil = 1; }
    else if (br == 1) { kb = dk2; vb = dv2; kstride = HD;   kofs = 0;   vofs = 0;   dil = 2; }
    else              { kb = dk3; vb = dv3; kstride = HD;   kofs = 0;   vofs = 0;   dil = 3; }

    const int qofs = br * 64;
    float2 q = __half22float2(*reinterpret_cast<const __half2*>(&qkv[pos * QKVC + qofs + 2 * lane]));

    float logits[9];
    #pragma unroll
    for (int kk = 0; kk < 9; kk++) {
        int y = h + (kk / 3 - 1) * dil;
        int xx = x + (kk % 3 - 1) * dil;
        float p = 0.f;
        if (y >= 0 && y < H_ && xx >= 0 && xx < W_) {
            const __half* kp = kb + ((b << 12) + (y << 6) + xx) * kstride + kofs;
            float2 kv = __half22float2(*reinterpret_cast<const __half2*>(&kp[2 * lane]));
            p = q.x * kv.x + q.y * kv.y;
        }
        #pragma unroll
        for (int s = 16; s; s >>= 1) p += __shfl_xor_sync(0xffffffffu, p, s);
        logits[kk] = p * 0.125f;
    }

    float mx = logits[0];
    #pragma unroll
    for (int kk = 1; kk < 9; kk++) mx = fmaxf(mx, logits[kk]);
    float e[9], den = 0.f;
    #pragma unroll
    for (int kk = 0; kk < 9; kk++) { e[kk] = __expf(logits[kk] - mx); den += e[kk]; }
    float inv = 1.f / den;

    float o0 = 0.f, o1 = 0.f;
    #pragma unroll
    for (int kk = 0; kk < 9; kk++) {
        int y = h + (kk / 3 - 1) * dil;
        int xx = x + (kk % 3 - 1) * dil;
        if (y >= 0 && y < H_ && xx >= 0 && xx < W_) {
            const __half* vp = vb + ((b << 12) + (y << 6) + xx) * kstride + vofs;
            float2 vv = __half22float2(*reinterpret_cast<const __half2*>(&vp[2 * lane]));
            float a = e[kk] * inv;
            o0 += a * vv.x;
            o1 += a * vv.y;
        }
    }
    *reinterpret_cast<__half2*>(&ob[pos * C_ + qofs + 2 * lane]) =
        __float22half2_rn(make_float2(o0, o1));
}

// ---------------------------------------------------------------------------
// Launch
// ---------------------------------------------------------------------------
extern "C" void kernel_launch(void* const* d_in, const int* in_sizes, int n_in,
                              void* d_out, int out_size)
{
    const float* x      = (const float*)d_in[0];
    const float* qkv_w  = (const float*)d_in[1];
    const float* proj_w = (const float*)d_in[2];
    const float* proj_b = (const float*)d_in[3];
    const float* off_w2 = (const float*)d_in[4];
    const float* off_b2 = (const float*)d_in[5];
    const float* def_w2 = (const float*)d_in[6];
    const float* def_b2 = (const float*)d_in[7];
    const float* off_w3 = (const float*)d_in[8];
    const float* off_b3 = (const float*)d_in[9];
    const float* def_w3 = (const float*)d_in[10];
    const float* def_b3 = (const float*)d_in[11];
    float* out = (float*)d_out;

    __half *p_qkv, *p_G, *p_dk2, *p_dv2, *p_dk3, *p_dv3, *p_attn, *p_wc;
    cudaGetSymbolAddress((void**)&p_qkv,  g_qkv);
    cudaGetSymbolAddress((void**)&p_G,    g_G);
    cudaGetSymbolAddress((void**)&p_dk2,  g_dk2);
    cudaGetSymbolAddress((void**)&p_dv2,  g_dv2);
    cudaGetSymbolAddress((void**)&p_dk3,  g_dk3);
    cudaGetSymbolAddress((void**)&p_dv3,  g_dv3);
    cudaGetSymbolAddress((void**)&p_attn, g_attn);
    cudaGetSymbolAddress((void**)&p_wc,   g_Wc);

    // 0) combined deform/offset weights (fp16)
    build_w<<<(2 * GN * HD + 255) / 256, 256>>>(def_w2, off_w2, def_w3, off_w3, p_wc);

    // 1) qkv = x @ qkv_w^T  -> fp16
    mma_qkv<<<dim3(QKVC / BN, M_ / BM), 128>>>(x, qkv_w, p_qkv);

    // 2) all four G projections (k2,v2,k3,v3) incl. fused offsets conv
    mma_g<<<dim3(GN / BN, M_ / BM, 4), 128>>>(p_qkv, p_wc, p_G);

    // 3) deformable gather, both branches -> fp16 dk/dv
    deform_gather<<<dim3(M_ / 8, 2), 256>>>(p_G, off_b2, def_b2, off_b3, def_b3,
                                            p_dk2, p_dv2, p_dk3, p_dv3);

    // 4) attention, all branches -> fp16 attn
    attn_all<<<dim3(M_ / 8, 3), 256>>>(p_qkv, p_dk2, p_dv2, p_dk3, p_dv3, p_attn);

    // 5) out = attn @ proj_w^T + proj_b  (fp32 out)
    mma_proj<<<dim3(C_ / BN, M_ / BM), 128>>>(p_attn, proj_w, proj_b, out);
}